// round 11
// baseline (speedup 1.0000x reference)
#include <cuda_runtime.h>
#include <cuda_fp16.h>
#include <cstdint>
#include <math.h>

// Shapes (fixed by the problem)
#define T_   4
#define B_   2048
#define D_   512
#define H_   8
#define TB_  8192          // T*B
#define DH_  4096          // D*H
#define BD_  1048576       // B*D
#define TBD_ 4194304       // T*B*D

static const size_t TBDH_ = (size_t)TB_ * DH_;  // 33,554,432

#define SCALE_DN 0.000244140625f   // 2^-12
#define SCALE_UP 4096.0f           // 2^12

// ---------------- scratch (static device globals; no allocation) ------------
__device__ __half g_xs[(size_t)TB_ * 512];           // shortcut spikes (single plane)
__device__ float g_ypre[3ULL * TB_ * DH_];           // pre-BN branch GEMM outputs
__device__ __half g_p[(size_t)TB_ * 4096];           // proj input spikes (single plane)
__device__ float g_opre[(size_t)TB_ * D_];           // pre-BN proj output
__device__ float g_mu[3 * DH_];
__device__ float g_rstd[3 * DH_];
__device__ float g_omu[D_];
__device__ float g_orstd[D_];
__device__ float g_part[3ULL * 128 * DH_ * 2];       // per-rowgroup (128) col partials
__device__ float g_opart[128ULL * D_ * 2];
__device__ __half g_wc[3ULL * DH_ * 1024];           // branch W': [n][hi*2^12 | mid']
__device__ __half g_wp[(size_t)D_ * 8192];           // proj  W': [n][hi*2^12 | mid']

// ======================= PTX helpers =========================================
__device__ __forceinline__ uint32_t smem_u32(const void* p) {
    uint32_t a;
    asm("{ .reg .u64 t; cvta.to.shared.u64 t, %1; cvt.u32.u64 %0, t; }" : "=r"(a) : "l"(p));
    return a;
}
__device__ __forceinline__ void cp16(uint32_t smem, const void* g) {
    asm volatile("cp.async.cg.shared.global [%0], [%1], 16;" :: "r"(smem), "l"(g));
}
#define CP_COMMIT() asm volatile("cp.async.commit_group;" ::: "memory")
#define CP_WAIT0()  asm volatile("cp.async.wait_group 0;" ::: "memory")
#define CP_WAIT1()  asm volatile("cp.async.wait_group 1;" ::: "memory")

__device__ __forceinline__ void ldm_x4(uint32_t* r, uint32_t addr) {
    asm volatile("ldmatrix.sync.aligned.m8n8.x4.shared.b16 {%0,%1,%2,%3}, [%4];"
                 : "=r"(r[0]), "=r"(r[1]), "=r"(r[2]), "=r"(r[3]) : "r"(addr));
}
__device__ __forceinline__ void mma16816(float* d, const uint32_t* a, const uint32_t* b) {
    asm volatile(
        "mma.sync.aligned.m16n8k16.row.col.f32.f16.f16.f32 "
        "{%0,%1,%2,%3}, {%4,%5,%6,%7}, {%8,%9}, {%0,%1,%2,%3};"
        : "+f"(d[0]), "+f"(d[1]), "+f"(d[2]), "+f"(d[3])
        : "r"(a[0]), "r"(a[1]), "r"(a[2]), "r"(a[3]), "r"(b[0]), "r"(b[1]));
}

// ======================= mma.sync fp16 GEMM + fused col stats ================
// C[M,N] = 2^-12 * (A[M,Ka] K-cycled to Keff) x (Bw[N,Keff])^T (+bias), fp32.
// Bw holds [hi*2^12 | mid'] planes; A is the raw spike plane (K-cycled).
// CTA tile 128x128, K-stage 64 in PADDED 144B rows (conflict-free, affine
// addressing), 8 warps (2x4, 64x32 each), 3-stage cp.async pipeline.
#define ROW_BYTES  144      // 128B data + 16B pad: banks (9r+c)%8 distinct
#define STAGE_BYTES (128 * ROW_BYTES)             // 18432
#define NSTAGE 3
#define GEMM_SMEM   (2 * NSTAGE * STAGE_BYTES)    // 110592

__global__ __launch_bounds__(256)
void k_mma_gemm(const __half* __restrict__ A,
                const __half* __restrict__ Bw,
                const float* __restrict__ bias,
                float* __restrict__ C,
                float* __restrict__ part,
                int N, int Ka, int Keff,
                size_t strideB, size_t strideC, size_t strideP)
{
    extern __shared__ __align__(128) char smem[];
    const uint32_t sA = smem_u32(smem);
    const uint32_t sB = sA + NSTAGE * STAGE_BYTES;
    const int tid  = threadIdx.x;
    const int wid  = tid >> 5, lane = tid & 31;
    const int wm   = wid >> 2, wn = wid & 3;

    Bw   += (size_t)blockIdx.z * strideB;
    C    += (size_t)blockIdx.z * strideC;
    part += (size_t)blockIdx.z * strideP;

    const __half* Ab = A  + (size_t)blockIdx.y * 128 * (size_t)Ka;
    const __half* Bb = Bw + (size_t)blockIdx.x * 128 * (size_t)Keff;
    const int S = Keff >> 6;

    float acc[4][4][4];
#pragma unroll
    for (int mi = 0; mi < 4; mi++)
#pragma unroll
        for (int ni = 0; ni < 4; ni++)
#pragma unroll
            for (int j = 0; j < 4; j++) acc[mi][ni][j] = 0.f;

    auto load_stage = [&](int s, int buf) {
        int kb  = s << 6;
        int kba = kb & (Ka - 1);               // A is K-cycled (Ka power of 2)
        const __half* Ag = Ab + kba;
        const __half* Bg = Bb + kb;
#pragma unroll
        for (int i = 0; i < 4; i++) {
            int q = tid + (i << 8);            // 0..1023 chunk id
            int r = q >> 3, c = q & 7;
            uint32_t off = (uint32_t)r * ROW_BYTES + (uint32_t)(c << 4);
            cp16(sA + buf * STAGE_BYTES + off, Ag + (size_t)r * Ka + (c << 3));
            cp16(sB + buf * STAGE_BYTES + off, Bg + (size_t)r * Keff + (c << 3));
        }
    };

    load_stage(0, 0);
    CP_COMMIT();
    if (S > 1) { load_stage(1, 1); CP_COMMIT(); }

    for (int s = 0; s < S; s++) {
        int buf = s % NSTAGE;
        if (s + 1 < S) CP_WAIT1(); else CP_WAIT0();
        __syncthreads();
        if (s + 2 < S) { load_stage(s + 2, (s + 2) % NSTAGE); CP_COMMIT(); }

        uint32_t bA = sA + buf * STAGE_BYTES;
        uint32_t bB = sB + buf * STAGE_BYTES;
#pragma unroll
        for (int kk = 0; kk < 4; kk++) {
            uint32_t afr[4][4];
#pragma unroll
            for (int mi = 0; mi < 4; mi++) {
                int row = wm * 64 + mi * 16 + (lane & 15);
                int c   = (kk << 1) + (lane >> 4);
                ldm_x4(afr[mi], bA + (uint32_t)row * ROW_BYTES + (uint32_t)(c << 4));
            }
            uint32_t bfr[4][2];
#pragma unroll
            for (int np = 0; np < 2; np++) {
                int g  = lane >> 3;                       // 0..3
                int nr = wn * 32 + np * 16 + ((g >> 1) << 3) + (lane & 7);
                int c  = (kk << 1) + (g & 1);
                uint32_t tmp[4];
                ldm_x4(tmp, bB + (uint32_t)nr * ROW_BYTES + (uint32_t)(c << 4));
                bfr[np * 2 + 0][0] = tmp[0]; bfr[np * 2 + 0][1] = tmp[1];
                bfr[np * 2 + 1][0] = tmp[2]; bfr[np * 2 + 1][1] = tmp[3];
            }
#pragma unroll
            for (int mi = 0; mi < 4; mi++)
#pragma unroll
                for (int ni = 0; ni < 4; ni++)
                    mma16816(acc[mi][ni], afr[mi], bfr[ni]);
        }
        // no bottom sync: buffer reuse distance is 3 stages; top barrier orders.
    }

    // ---------------- epilogue: unscale, bias, store C, fused col stats ----
#pragma unroll
    for (int mi = 0; mi < 4; mi++)
#pragma unroll
        for (int ni = 0; ni < 4; ni++)
#pragma unroll
            for (int j = 0; j < 4; j++) acc[mi][ni][j] *= SCALE_DN;  // exact 2^-12

    int grow = lane >> 2;
    int gcol = (lane & 3) * 2;
    if (bias) {
#pragma unroll
        for (int ni = 0; ni < 4; ni++) {
            int cc = blockIdx.x * 128 + wn * 32 + ni * 8 + gcol;
            float b0 = bias[cc], b1 = bias[cc + 1];
#pragma unroll
            for (int mi = 0; mi < 4; mi++) {
                acc[mi][ni][0] += b0; acc[mi][ni][1] += b1;
                acc[mi][ni][2] += b0; acc[mi][ni][3] += b1;
            }
        }
    }
#pragma unroll
    for (int mi = 0; mi < 4; mi++) {
        int r0 = blockIdx.y * 128 + wm * 64 + mi * 16 + grow;
#pragma unroll
        for (int ni = 0; ni < 4; ni++) {
            int cc = blockIdx.x * 128 + wn * 32 + ni * 8 + gcol;
            *reinterpret_cast<float2*>(C + (size_t)r0 * N + cc) =
                make_float2(acc[mi][ni][0], acc[mi][ni][1]);
            *reinterpret_cast<float2*>(C + (size_t)(r0 + 8) * N + cc) =
                make_float2(acc[mi][ni][2], acc[mi][ni][3]);
        }
    }
    int rowgrp = blockIdx.y * 2 + wm;
#pragma unroll
    for (int ni = 0; ni < 4; ni++) {
#pragma unroll
        for (int jj = 0; jj < 2; jj++) {
            float s = 0.f, q = 0.f;
#pragma unroll
            for (int mi = 0; mi < 4; mi++) {
                float v0 = acc[mi][ni][jj], v1 = acc[mi][ni][jj + 2];
                s += v0 + v1;
                q += v0 * v0 + v1 * v1;
            }
#pragma unroll
            for (int o = 4; o < 32; o <<= 1) {
                s += __shfl_xor_sync(0xffffffffu, s, o);
                q += __shfl_xor_sync(0xffffffffu, q, o);
            }
            if (grow == 0) {
                int cc = blockIdx.x * 128 + wn * 32 + ni * 8 + gcol + jj;
                size_t idx = ((size_t)rowgrp * N + cc) * 2;
                part[idx]     = s;
                part[idx + 1] = q;
            }
        }
    }
}

// ======================= stats finalize (merged over branches via y) =========
__global__ void k_colstats_fin(const float* __restrict__ part,
                               float* __restrict__ mu, float* __restrict__ rstd,
                               int cols, size_t pstride) {
    part += (size_t)blockIdx.y * pstride;
    mu   += (size_t)blockIdx.y * cols;
    rstd += (size_t)blockIdx.y * cols;
    int c = blockIdx.x * 256 + threadIdx.x;
    if (c >= cols) return;
    float s = 0.f, cs = 0.f, q = 0.f, cq = 0.f;
    for (int rg = 0; rg < 128; rg++) {
        float vs = part[((size_t)rg * cols + c) * 2 + 0];
        float vq = part[((size_t)rg * cols + c) * 2 + 1];
        float y1 = vs - cs; float t1 = s + y1; cs = (t1 - s) - y1; s = t1;
        float y2 = vq - cq; float t2 = q + y2; cq = (t2 - q) - y2; q = t2;
    }
    const float invn = 1.0f / 8192.0f;
    float m = s * invn;
    float var = q * invn - m * m;
    mu[c] = m;
    rstd[c] = 1.0f / sqrtf(var + 1e-5f);
}

// ======================= weight split2: [hi*2^12 | mid'], vec x4 =============
__global__ void k_split2(const float* __restrict__ w0, const float* __restrict__ w1,
                         const float* __restrict__ w2, __half* __restrict__ dst,
                         int NK, int K, size_t dstride) {
    int i4 = (blockIdx.x * 256 + threadIdx.x) * 4;
    if (i4 >= NK) return;
    const float* w = (blockIdx.y == 0) ? w0 : (blockIdx.y == 1) ? w1 : w2;
    __half* d = dst + (size_t)blockIdx.y * dstride;
    int n = i4 / K, kk = i4 - n * K;      // 4 consecutive kk (K % 4 == 0)
    float4 v = *reinterpret_cast<const float4*>(w + i4);
    float vv[4] = { v.x, v.y, v.z, v.w };
    __half hs[4], m[4];
#pragma unroll
    for (int j = 0; j < 4; j++) {
        __half h = __float2half_rn(vv[j]);
        float hf = __half2float(h);
        hs[j] = __float2half_rn(hf * SCALE_UP);              // hi*2^12, exact
        m[j]  = __float2half_rn((vv[j] - hf) * SCALE_UP);    // mid', as before
    }
    size_t base = (size_t)n * 2 * K + kk;
    *reinterpret_cast<uint2*>(d + base)     = *reinterpret_cast<uint2*>(hs);
    *reinterpret_cast<uint2*>(d + base + K) = *reinterpret_cast<uint2*>(m);
}

// ======================= elementwise stages ==================================
// shortcut LIF -> single-plane half spikes, 4 elements/thread
__global__ void k_lif_in(const float* __restrict__ x) {
    int i4 = (blockIdx.x * 256 + threadIdx.x) * 4;
    if (i4 >= BD_) return;
    int b = i4 >> 9, d2 = i4 & 511;
    float v[4] = { 0.f, 0.f, 0.f, 0.f };
#pragma unroll
    for (int t = 0; t < T_; t++) {
        float4 xt = *reinterpret_cast<const float4*>(x + t * BD_ + i4);
        float xv[4] = { xt.x, xt.y, xt.z, xt.w };
        __half s[4];
#pragma unroll
        for (int j = 0; j < 4; j++) {
            float dta = xv[j] - v[j];
            v[j] = v[j] + dta * 0.5f;
            float sp = (v[j] - 1.0f) >= 0.0f ? 1.0f : 0.0f;
            s[j] = __float2half(sp);
            v[j] = v[j] * (1.0f - sp);
        }
        size_t base = ((size_t)(t * B_ + b)) * 512 + d2;
        *reinterpret_cast<uint2*>(g_xs + base) = *reinterpret_cast<uint2*>(s);
    }
}

// mega-fused: BN+LIF for q,k,v + kv-sum + kv-LIF(0.5) + p = q*kvs (single plane)
__global__ __launch_bounds__(128)
void k_bnlif_kv(const float* __restrict__ Y,
                const float* __restrict__ mu, const float* __restrict__ rstd,
                const float* __restrict__ gq, const float* __restrict__ bq,
                const float* __restrict__ gk, const float* __restrict__ bk,
                const float* __restrict__ gv, const float* __restrict__ bv,
                float* __restrict__ vout, __half* __restrict__ P)
{
    int i = blockIdx.x * 128 + threadIdx.x;
    if (i >= BD_) return;
    int b = i >> 9, dd = i & 511;
    int c0 = dd << 3;

    const float* Yb[3] = { Y, Y + TBDH_, Y + 2 * TBDH_ };
    const float* gs[3] = { gq, gk, gv };
    const float* bs[3] = { bq, bk, bv };
    float prm[3][4][8];
#pragma unroll
    for (int br = 0; br < 3; br++)
#pragma unroll
        for (int h = 0; h < 8; h++) {
            prm[br][0][h] = mu[br * DH_ + c0 + h];
            prm[br][1][h] = rstd[br * DH_ + c0 + h];
            prm[br][2][h] = gs[br][c0 + h];
            prm[br][3][h] = bs[br][c0 + h];
        }

    float uq[8], uk[8], uv[8], ukv = 0.f;
#pragma unroll
    for (int h = 0; h < 8; h++) { uq[h] = uk[h] = uv[h] = 0.f; }

#pragma unroll
    for (int t = 0; t < T_; t++) {
        int row = t * B_ + b;
        size_t rb = (size_t)row * DH_ + c0;
        float xq[8], xk[8], xv[8];
        *reinterpret_cast<float4*>(&xq[0]) = *reinterpret_cast<const float4*>(Yb[0] + rb);
        *reinterpret_cast<float4*>(&xq[4]) = *reinterpret_cast<const float4*>(Yb[0] + rb + 4);
        *reinterpret_cast<float4*>(&xk[0]) = *reinterpret_cast<const float4*>(Yb[1] + rb);
        *reinterpret_cast<float4*>(&xk[4]) = *reinterpret_cast<const float4*>(Yb[1] + rb + 4);
        *reinterpret_cast<float4*>(&xv[0]) = *reinterpret_cast<const float4*>(Yb[2] + rb);
        *reinterpret_cast<float4*>(&xv[4]) = *reinterpret_cast<const float4*>(Yb[2] + rb + 4);

        float sq[8];
        float kv = 0.f;
        size_t ob = (size_t)row * DH_ + dd;
#pragma unroll
        for (int h = 0; h < 8; h++) {
            float y = prm[0][2][h] * (xq[h] - prm[0][0][h]); y *= prm[0][1][h]; y += prm[0][3][h];
            float d = y - uq[h]; uq[h] = uq[h] + d * 0.5f;
            float s = (uq[h] - 1.0f) >= 0.f ? 1.f : 0.f; sq[h] = s; uq[h] *= (1.f - s);
            y = prm[1][2][h] * (xk[h] - prm[1][0][h]); y *= prm[1][1][h]; y += prm[1][3][h];
            d = y - uk[h]; uk[h] = uk[h] + d * 0.5f;
            float sk = (uk[h] - 1.0f) >= 0.f ? 1.f : 0.f; uk[h] *= (1.f - sk);
            y = prm[2][2][h] * (xv[h] - prm[2][0][h]); y *= prm[2][1][h]; y += prm[2][3][h];
            d = y - uv[h]; uv[h] = uv[h] + d * 0.5f;
            float sv = (uv[h] - 1.0f) >= 0.f ? 1.f : 0.f; uv[h] *= (1.f - sv);

            vout[ob + (h << 9)] = sv;
            kv += sk * sv;
        }
        float d2 = kv - ukv; ukv = ukv + d2 * 0.5f;
        float skv = (ukv - 0.5f) >= 0.f ? 1.f : 0.f; ukv *= (1.f - skv);

        size_t pb = (size_t)row * 4096 + dd;
#pragma unroll
        for (int h = 0; h < 8; h++)
            P[pb + (h << 9)] = __float2half(sq[h] * skv);
    }
}

// final BN + residual, 4 elements/thread
__global__ void k_bn_add(const float* __restrict__ x, const float* __restrict__ gp,
                         const float* __restrict__ bp, float* __restrict__ out) {
    int i4 = (blockIdx.x * 256 + threadIdx.x) * 4;
    if (i4 >= TBD_) return;
    int c = i4 & 511;
    float4 v  = *reinterpret_cast<const float4*>(g_opre + i4);
    float4 xr = *reinterpret_cast<const float4*>(x + i4);
    float4 mg = *reinterpret_cast<const float4*>(g_omu + c);
    float4 rg = *reinterpret_cast<const float4*>(g_orstd + c);
    float4 gg = *reinterpret_cast<const float4*>(gp + c);
    float4 bb = *reinterpret_cast<const float4*>(bp + c);
    float vv[4] = { v.x, v.y, v.z, v.w };
    float xx[4] = { xr.x, xr.y, xr.z, xr.w };
    float mm[4] = { mg.x, mg.y, mg.z, mg.w };
    float rr[4] = { rg.x, rg.y, rg.z, rg.w };
    float ga[4] = { gg.x, gg.y, gg.z, gg.w };
    float ba[4] = { bb.x, bb.y, bb.z, bb.w };
    float o[4];
#pragma unroll
    for (int j = 0; j < 4; j++) {
        float y = ga[j] * (vv[j] - mm[j]);
        y = y * rr[j];
        y = y + ba[j];
        o[j] = y + xx[j];
    }
    *reinterpret_cast<float4*>(out + i4) =
        make_float4(o[0], o[1], o[2], o[3]);
}

// ======================= launch ==============================================
extern "C" void kernel_launch(void* const* d_in, const int* in_sizes, int n_in,
                              void* d_out, int out_size) {
    const float* x     = (const float*)d_in[0];
    const float* wq    = (const float*)d_in[1];
    const float* gq    = (const float*)d_in[2];
    const float* bq    = (const float*)d_in[3];
    const float* wk    = (const float*)d_in[4];
    const float* gk    = (const float*)d_in[5];
    const float* bk    = (const float*)d_in[6];
    const float* wv    = (const float*)d_in[7];
    const float* gv    = (const float*)d_in[8];
    const float* bv    = (const float*)d_in[9];
    const float* wproj = (const float*)d_in[10];
    const float* bproj = (const float*)d_in[11];
    const float* gp    = (const float*)d_in[12];
    const float* bp    = (const float*)d_in[13];

    float* out  = (float*)d_out;
    float* vout = out + TBD_;

    __half *p_xs, *p_p, *p_wc, *p_wp;
    float *p_ypre, *p_opre;
    float *p_mu, *p_rstd, *p_omu, *p_orstd, *p_part, *p_opart;
    cudaGetSymbolAddress((void**)&p_xs,    g_xs);
    cudaGetSymbolAddress((void**)&p_ypre,  g_ypre);
    cudaGetSymbolAddress((void**)&p_p,     g_p);
    cudaGetSymbolAddress((void**)&p_opre,  g_opre);
    cudaGetSymbolAddress((void**)&p_mu,    g_mu);
    cudaGetSymbolAddress((void**)&p_rstd,  g_rstd);
    cudaGetSymbolAddress((void**)&p_omu,   g_omu);
    cudaGetSymbolAddress((void**)&p_orstd, g_orstd);
    cudaGetSymbolAddress((void**)&p_part,  g_part);
    cudaGetSymbolAddress((void**)&p_opart, g_opart);
    cudaGetSymbolAddress((void**)&p_wc,    g_wc);
    cudaGetSymbolAddress((void**)&p_wp,    g_wp);

    cudaFuncSetAttribute(k_mma_gemm, cudaFuncAttributeMaxDynamicSharedMemorySize,
                         GEMM_SMEM);

    // 0) split fp32 weights into [hi*2^12 | mid'] fp16 planes, vec x4
    const int nkb = DH_ * D_;
    k_split2<<<dim3((nkb / 4 + 255) / 256, 3), 256>>>(wq, wk, wv, p_wc, nkb, D_,
                                                      (size_t)DH_ * 1024);
    k_split2<<<dim3((nkb / 4 + 255) / 256, 1), 256>>>(wproj, wproj, wproj, p_wp,
                                                      nkb, DH_, 0);

    // 1) shortcut LIF -> single-plane half spikes, vec x4
    k_lif_in<<<BD_ / 1024, 256>>>(x);

    // 2) three branch GEMMs in one launch (z = branch), Ka=512 cycled to 1024
    const size_t PSTRIDE = 128ULL * DH_ * 2;
    k_mma_gemm<<<dim3(DH_ / 128, TB_ / 128, 3), 256, GEMM_SMEM>>>(
        p_xs, p_wc, nullptr, p_ypre, p_part,
        DH_, 512, 1024, (size_t)DH_ * 1024, TBDH_, PSTRIDE);

    // 3) finalize BN stats for all 3 branches in one launch
    k_colstats_fin<<<dim3(DH_ / 256, 3), 256>>>(p_part, p_mu, p_rstd, DH_, PSTRIDE);

    // 4) mega-fused BN+LIF(q,k,v) + kv + LIF(0.5) + p
    k_bnlif_kv<<<BD_ / 128, 128>>>(p_ypre, p_mu, p_rstd, gq, bq, gk, bk, gv, bv,
                                   vout, p_p);

    // 5) proj GEMM: Ka=4096 cycled to 8192 (+bias), stats fused
    k_mma_gemm<<<dim3(D_ / 128, TB_ / 128, 1), 256, GEMM_SMEM>>>(
        p_p, p_wp, bproj, p_opre, p_opart,
        D_, 4096, 8192, 0, 0, 0);

    // 6) finalize proj stats
    k_colstats_fin<<<dim3(D_ / 256, 1), 256>>>(p_opart, p_omu, p_orstd, D_, 0);

    // 7) final BN + residual, vec x4
    k_bn_add<<<TBD_ / 1024, 256>>>(x, gp, bp, out);
}

// round 12
// speedup vs baseline: 1.0634x; 1.0634x over previous
#include <cuda_runtime.h>
#include <cuda_fp16.h>
#include <cstdint>
#include <math.h>

// Shapes (fixed by the problem)
#define T_   4
#define B_   2048
#define D_   512
#define H_   8
#define TB_  8192          // T*B
#define DH_  4096          // D*H
#define BD_  1048576       // B*D
#define TBD_ 4194304       // T*B*D

static const size_t TBDH_ = (size_t)TB_ * DH_;  // 33,554,432

#define SCALE_DN 0.000244140625f   // 2^-12
#define SCALE_UP 4096.0f           // 2^12

// ---------------- scratch (static device globals; no allocation) ------------
__device__ __half g_xs[(size_t)TB_ * 1024];          // shortcut spikes dual-half
__device__ float g_ypre[3ULL * TB_ * DH_];           // pre-BN branch GEMM outputs
__device__ __half g_p[(size_t)TB_ * 8192];           // proj input dual-half
__device__ float g_opre[(size_t)TB_ * D_];           // pre-BN proj output
__device__ float g_mu[3 * DH_];
__device__ float g_rstd[3 * DH_];
__device__ float g_omu[D_];
__device__ float g_orstd[D_];
__device__ float g_part[3ULL * 128 * DH_ * 2];       // per-rowgroup (128) col partials
__device__ float g_opart[128ULL * D_ * 2];
__device__ __half g_wc[3ULL * DH_ * 1024];           // branch weights split2
__device__ __half g_wp[(size_t)D_ * 8192];           // proj weights split2

// ======================= PTX helpers =========================================
__device__ __forceinline__ uint32_t smem_u32(const void* p) {
    uint32_t a;
    asm("{ .reg .u64 t; cvta.to.shared.u64 t, %1; cvt.u32.u64 %0, t; }" : "=r"(a) : "l"(p));
    return a;
}
__device__ __forceinline__ void cp16(uint32_t smem, const void* g) {
    asm volatile("cp.async.cg.shared.global [%0], [%1], 16;" :: "r"(smem), "l"(g));
}
#define CP_COMMIT() asm volatile("cp.async.commit_group;" ::: "memory")
#define CP_WAIT0()  asm volatile("cp.async.wait_group 0;" ::: "memory")
#define CP_WAIT1()  asm volatile("cp.async.wait_group 1;" ::: "memory")

__device__ __forceinline__ void ldm_x4(uint32_t* r, uint32_t addr) {
    asm volatile("ldmatrix.sync.aligned.m8n8.x4.shared.b16 {%0,%1,%2,%3}, [%4];"
                 : "=r"(r[0]), "=r"(r[1]), "=r"(r[2]), "=r"(r[3]) : "r"(addr));
}
__device__ __forceinline__ void mma16816(float* d, const uint32_t* a, const uint32_t* b) {
    asm volatile(
        "mma.sync.aligned.m16n8k16.row.col.f32.f16.f16.f32 "
        "{%0,%1,%2,%3}, {%4,%5,%6,%7}, {%8,%9}, {%0,%1,%2,%3};"
        : "+f"(d[0]), "+f"(d[1]), "+f"(d[2]), "+f"(d[3])
        : "r"(a[0]), "r"(a[1]), "r"(a[2]), "r"(a[3]), "r"(b[0]), "r"(b[1]));
}

// ======================= mma.sync fp16 GEMM + fused col stats ================
// CTA tile 128x128, K-stage 64 (128B swizzled rows), 8 warps (2x4, 64x32 each),
// 3-stage cp.async pipeline.  (Round-10 proven configuration.)
#define STAGE_BYTES 16384   // 128 rows * 128B
#define NSTAGE 3
#define GEMM_SMEM   (2 * NSTAGE * STAGE_BYTES)   // 98304

__global__ __launch_bounds__(256)
void k_mma_gemm(const __half* __restrict__ A,
                const __half* __restrict__ Bw,
                const float* __restrict__ bias,
                float* __restrict__ C,
                float* __restrict__ part,
                int N, int Keff,
                size_t strideB, size_t strideC, size_t strideP)
{
    extern __shared__ __align__(128) char smem[];
    const uint32_t sA = smem_u32(smem);
    const uint32_t sB = sA + NSTAGE * STAGE_BYTES;
    const int tid  = threadIdx.x;
    const int wid  = tid >> 5, lane = tid & 31;
    const int wm   = wid >> 2, wn = wid & 3;

    Bw   += (size_t)blockIdx.z * strideB;
    C    += (size_t)blockIdx.z * strideC;
    part += (size_t)blockIdx.z * strideP;

    const __half* Ab = A  + (size_t)blockIdx.y * 128 * (size_t)Keff;
    const __half* Bb = Bw + (size_t)blockIdx.x * 128 * (size_t)Keff;
    const int S = Keff >> 6;

    float acc[4][4][4];
#pragma unroll
    for (int mi = 0; mi < 4; mi++)
#pragma unroll
        for (int ni = 0; ni < 4; ni++)
#pragma unroll
            for (int j = 0; j < 4; j++) acc[mi][ni][j] = 0.f;

    auto load_stage = [&](int s, int buf) {
        int kb = s << 6;
        const __half* Ag = Ab + kb;
        const __half* Bg = Bb + kb;
#pragma unroll
        for (int i = 0; i < 4; i++) {
            int q = tid + (i << 8);            // 0..1023 chunk id
            int r = q >> 3, c = q & 7;
            uint32_t off = (uint32_t)r * 128 + (uint32_t)((c ^ (r & 7)) << 4);
            cp16(sA + buf * STAGE_BYTES + off, Ag + (size_t)r * Keff + (c << 3));
            cp16(sB + buf * STAGE_BYTES + off, Bg + (size_t)r * Keff + (c << 3));
        }
    };

    load_stage(0, 0);
    CP_COMMIT();
    if (S > 1) { load_stage(1, 1); CP_COMMIT(); }

    for (int s = 0; s < S; s++) {
        int buf = s % NSTAGE;
        if (s + 1 < S) CP_WAIT1(); else CP_WAIT0();
        __syncthreads();
        if (s + 2 < S) { load_stage(s + 2, (s + 2) % NSTAGE); CP_COMMIT(); }

        uint32_t bA = sA + buf * STAGE_BYTES;
        uint32_t bB = sB + buf * STAGE_BYTES;
#pragma unroll
        for (int kk = 0; kk < 4; kk++) {
            uint32_t afr[4][4];
#pragma unroll
            for (int mi = 0; mi < 4; mi++) {
                int row = wm * 64 + mi * 16 + (lane & 15);
                int c   = (kk << 1) + (lane >> 4);
                ldm_x4(afr[mi], bA + (uint32_t)row * 128 + (uint32_t)((c ^ (row & 7)) << 4));
            }
            uint32_t bfr[4][2];
#pragma unroll
            for (int np = 0; np < 2; np++) {
                int g  = lane >> 3;                       // 0..3
                int nr = wn * 32 + np * 16 + (g >> 1) * 8 + (lane & 7);
                int c  = (kk << 1) + (g & 1);
                uint32_t tmp[4];
                ldm_x4(tmp, bB + (uint32_t)nr * 128 + (uint32_t)((c ^ (nr & 7)) << 4));
                bfr[np * 2 + 0][0] = tmp[0]; bfr[np * 2 + 0][1] = tmp[1];
                bfr[np * 2 + 1][0] = tmp[2]; bfr[np * 2 + 1][1] = tmp[3];
            }
#pragma unroll
            for (int mi = 0; mi < 4; mi++)
#pragma unroll
                for (int ni = 0; ni < 4; ni++)
                    mma16816(acc[mi][ni], afr[mi], bfr[ni]);
        }
        // no bottom sync: buffer reuse distance is 3 stages; top barrier orders.
    }

    // ---------------- epilogue: bias, store C, fused column stats ----------
    int grow = lane >> 2;
    int gcol = (lane & 3) * 2;
    if (bias) {
#pragma unroll
        for (int ni = 0; ni < 4; ni++) {
            int cc = blockIdx.x * 128 + wn * 32 + ni * 8 + gcol;
            float b0 = bias[cc], b1 = bias[cc + 1];
#pragma unroll
            for (int mi = 0; mi < 4; mi++) {
                acc[mi][ni][0] += b0; acc[mi][ni][1] += b1;
                acc[mi][ni][2] += b0; acc[mi][ni][3] += b1;
            }
        }
    }
#pragma unroll
    for (int mi = 0; mi < 4; mi++) {
        int r0 = blockIdx.y * 128 + wm * 64 + mi * 16 + grow;
#pragma unroll
        for (int ni = 0; ni < 4; ni++) {
            int cc = blockIdx.x * 128 + wn * 32 + ni * 8 + gcol;
            *reinterpret_cast<float2*>(C + (size_t)r0 * N + cc) =
                make_float2(acc[mi][ni][0], acc[mi][ni][1]);
            *reinterpret_cast<float2*>(C + (size_t)(r0 + 8) * N + cc) =
                make_float2(acc[mi][ni][2], acc[mi][ni][3]);
        }
    }
    int rowgrp = blockIdx.y * 2 + wm;
#pragma unroll
    for (int ni = 0; ni < 4; ni++) {
#pragma unroll
        for (int jj = 0; jj < 2; jj++) {
            float s = 0.f, q = 0.f;
#pragma unroll
            for (int mi = 0; mi < 4; mi++) {
                float v0 = acc[mi][ni][jj], v1 = acc[mi][ni][jj + 2];
                s += v0 + v1;
                q += v0 * v0 + v1 * v1;
            }
#pragma unroll
            for (int o = 4; o < 32; o <<= 1) {
                s += __shfl_xor_sync(0xffffffffu, s, o);
                q += __shfl_xor_sync(0xffffffffu, q, o);
            }
            if (grow == 0) {
                int cc = blockIdx.x * 128 + wn * 32 + ni * 8 + gcol + jj;
                size_t idx = ((size_t)rowgrp * N + cc) * 2;
                part[idx]     = s;
                part[idx + 1] = q;
            }
        }
    }
}

// ======================= stats finalize (merged over branches via y) =========
__global__ void k_colstats_fin(const float* __restrict__ part,
                               float* __restrict__ mu, float* __restrict__ rstd,
                               int cols, size_t pstride) {
    part += (size_t)blockIdx.y * pstride;
    mu   += (size_t)blockIdx.y * cols;
    rstd += (size_t)blockIdx.y * cols;
    int c = blockIdx.x * 256 + threadIdx.x;
    if (c >= cols) return;
    float s = 0.f, cs = 0.f, q = 0.f, cq = 0.f;
    for (int rg = 0; rg < 128; rg++) {
        float vs = part[((size_t)rg * cols + c) * 2 + 0];
        float vq = part[((size_t)rg * cols + c) * 2 + 1];
        float y1 = vs - cs; float t1 = s + y1; cs = (t1 - s) - y1; s = t1;
        float y2 = vq - cq; float t2 = q + y2; cq = (t2 - q) - y2; q = t2;
    }
    const float invn = 1.0f / 8192.0f;
    float m = s * invn;
    float var = q * invn - m * m;
    mu[c] = m;
    rstd[c] = 1.0f / sqrtf(var + 1e-5f);
}

// ======================= weight split2 (fp16 hi + fp16 mid*4096), vec x4 =====
__global__ void k_split2(const float* __restrict__ w0, const float* __restrict__ w1,
                         const float* __restrict__ w2, __half* __restrict__ dst,
                         int NK, int K, size_t dstride) {
    int i4 = (blockIdx.x * 256 + threadIdx.x) * 4;
    if (i4 >= NK) return;
    const float* w = (blockIdx.y == 0) ? w0 : (blockIdx.y == 1) ? w1 : w2;
    __half* d = dst + (size_t)blockIdx.y * dstride;
    int n = i4 / K, kk = i4 - n * K;      // 4 consecutive kk (K % 4 == 0)
    float4 v = *reinterpret_cast<const float4*>(w + i4);
    float vv[4] = { v.x, v.y, v.z, v.w };
    __half h[4], m[4];
#pragma unroll
    for (int j = 0; j < 4; j++) {
        h[j] = __float2half_rn(vv[j]);
        float r1 = vv[j] - __half2float(h[j]);
        m[j] = __float2half_rn(r1 * SCALE_UP);
    }
    size_t base = (size_t)n * 2 * K + kk;
    *reinterpret_cast<uint2*>(d + base)     = *reinterpret_cast<uint2*>(h);
    *reinterpret_cast<uint2*>(d + base + K) = *reinterpret_cast<uint2*>(m);
}

// ======================= elementwise stages ==================================
// shortcut LIF -> dual-half spikes, 4 elements/thread (d2 consecutive)
__global__ void k_lif_in(const float* __restrict__ x) {
    int i4 = (blockIdx.x * 256 + threadIdx.x) * 4;
    if (i4 >= BD_) return;
    int b = i4 >> 9, d2 = i4 & 511;       // 4 consecutive d2 (512 % 4 == 0)
    float v[4] = { 0.f, 0.f, 0.f, 0.f };
#pragma unroll
    for (int t = 0; t < T_; t++) {
        float4 xt = *reinterpret_cast<const float4*>(x + t * BD_ + i4);
        float xv[4] = { xt.x, xt.y, xt.z, xt.w };
        __half s[4], sd[4];
#pragma unroll
        for (int j = 0; j < 4; j++) {
            float dta = xv[j] - v[j];
            v[j] = v[j] + dta * 0.5f;
            float sp = (v[j] - 1.0f) >= 0.0f ? 1.0f : 0.0f;
            s[j]  = __float2half(sp);
            sd[j] = __float2half(sp * SCALE_DN);
            v[j] = v[j] * (1.0f - sp);
        }
        size_t base = ((size_t)(t * B_ + b)) * 1024 + d2;
        *reinterpret_cast<uint2*>(g_xs + base)       = *reinterpret_cast<uint2*>(s);
        *reinterpret_cast<uint2*>(g_xs + base + 512) = *reinterpret_cast<uint2*>(sd);
    }
}

// mega-fused: BN+LIF for q,k,v + kv-sum + kv-LIF(0.5) + p = q*kvs (dual-half)
__global__ __launch_bounds__(256)
void k_bnlif_kv(const float* __restrict__ Y,
                const float* __restrict__ mu, const float* __restrict__ rstd,
                const float* __restrict__ gq, const float* __restrict__ bq,
                const float* __restrict__ gk, const float* __restrict__ bk,
                const float* __restrict__ gv, const float* __restrict__ bv,
                float* __restrict__ vout, __half* __restrict__ P)
{
    int i = blockIdx.x * 256 + threadIdx.x;
    if (i >= BD_) return;
    int b = i >> 9, dd = i & 511;
    int c0 = dd << 3;

    const float* Yb[3] = { Y, Y + TBDH_, Y + 2 * TBDH_ };
    const float* gs[3] = { gq, gk, gv };
    const float* bs[3] = { bq, bk, bv };
    float prm[3][4][8];
#pragma unroll
    for (int br = 0; br < 3; br++)
#pragma unroll
        for (int h = 0; h < 8; h++) {
            prm[br][0][h] = mu[br * DH_ + c0 + h];
            prm[br][1][h] = rstd[br * DH_ + c0 + h];
            prm[br][2][h] = gs[br][c0 + h];
            prm[br][3][h] = bs[br][c0 + h];
        }

    float uq[8], uk[8], uv[8], ukv = 0.f;
#pragma unroll
    for (int h = 0; h < 8; h++) { uq[h] = uk[h] = uv[h] = 0.f; }

#pragma unroll
    for (int t = 0; t < T_; t++) {
        int row = t * B_ + b;
        size_t rb = (size_t)row * DH_ + c0;
        float xq[8], xk[8], xv[8];
        *reinterpret_cast<float4*>(&xq[0]) = *reinterpret_cast<const float4*>(Yb[0] + rb);
        *reinterpret_cast<float4*>(&xq[4]) = *reinterpret_cast<const float4*>(Yb[0] + rb + 4);
        *reinterpret_cast<float4*>(&xk[0]) = *reinterpret_cast<const float4*>(Yb[1] + rb);
        *reinterpret_cast<float4*>(&xk[4]) = *reinterpret_cast<const float4*>(Yb[1] + rb + 4);
        *reinterpret_cast<float4*>(&xv[0]) = *reinterpret_cast<const float4*>(Yb[2] + rb);
        *reinterpret_cast<float4*>(&xv[4]) = *reinterpret_cast<const float4*>(Yb[2] + rb + 4);

        float sq[8];
        float kv = 0.f;
        size_t ob = (size_t)row * DH_ + dd;
#pragma unroll
        for (int h = 0; h < 8; h++) {
            float y = prm[0][2][h] * (xq[h] - prm[0][0][h]); y *= prm[0][1][h]; y += prm[0][3][h];
            float d = y - uq[h]; uq[h] = uq[h] + d * 0.5f;
            float s = (uq[h] - 1.0f) >= 0.f ? 1.f : 0.f; sq[h] = s; uq[h] *= (1.f - s);
            y = prm[1][2][h] * (xk[h] - prm[1][0][h]); y *= prm[1][1][h]; y += prm[1][3][h];
            d = y - uk[h]; uk[h] = uk[h] + d * 0.5f;
            float sk = (uk[h] - 1.0f) >= 0.f ? 1.f : 0.f; uk[h] *= (1.f - sk);
            y = prm[2][2][h] * (xv[h] - prm[2][0][h]); y *= prm[2][1][h]; y += prm[2][3][h];
            d = y - uv[h]; uv[h] = uv[h] + d * 0.5f;
            float sv = (uv[h] - 1.0f) >= 0.f ? 1.f : 0.f; uv[h] *= (1.f - sv);

            vout[ob + (h << 9)] = sv;
            kv += sk * sv;
        }
        float d2 = kv - ukv; ukv = ukv + d2 * 0.5f;
        float skv = (ukv - 0.5f) >= 0.f ? 1.f : 0.f; ukv *= (1.f - skv);

        size_t pb = (size_t)row * 8192 + dd;
#pragma unroll
        for (int h = 0; h < 8; h++) {
            float pv = sq[h] * skv;
            P[pb + (h << 9)]        = __float2half(pv);
            P[pb + 4096 + (h << 9)] = __float2half(pv * SCALE_DN);
        }
    }
}

// final BN + residual, 4 elements/thread
__global__ void k_bn_add(const float* __restrict__ x, const float* __restrict__ gp,
                         const float* __restrict__ bp, float* __restrict__ out) {
    int i4 = (blockIdx.x * 256 + threadIdx.x) * 4;
    if (i4 >= TBD_) return;
    int c = i4 & 511;                     // 4 consecutive channels
    float4 v  = *reinterpret_cast<const float4*>(g_opre + i4);
    float4 xr = *reinterpret_cast<const float4*>(x + i4);
    float4 mg = *reinterpret_cast<const float4*>(g_omu + c);
    float4 rg = *reinterpret_cast<const float4*>(g_orstd + c);
    float4 gg = *reinterpret_cast<const float4*>(gp + c);
    float4 bb = *reinterpret_cast<const float4*>(bp + c);
    float vv[4] = { v.x, v.y, v.z, v.w };
    float xx[4] = { xr.x, xr.y, xr.z, xr.w };
    float mm[4] = { mg.x, mg.y, mg.z, mg.w };
    float rr[4] = { rg.x, rg.y, rg.z, rg.w };
    float ga[4] = { gg.x, gg.y, gg.z, gg.w };
    float ba[4] = { bb.x, bb.y, bb.z, bb.w };
    float o[4];
#pragma unroll
    for (int j = 0; j < 4; j++) {
        float y = ga[j] * (vv[j] - mm[j]);
        y = y * rr[j];
        y = y + ba[j];
        o[j] = y + xx[j];
    }
    *reinterpret_cast<float4*>(out + i4) =
        make_float4(o[0], o[1], o[2], o[3]);
}

// ======================= launch ==============================================
extern "C" void kernel_launch(void* const* d_in, const int* in_sizes, int n_in,
                              void* d_out, int out_size) {
    const float* x     = (const float*)d_in[0];
    const float* wq    = (const float*)d_in[1];
    const float* gq    = (const float*)d_in[2];
    const float* bq    = (const float*)d_in[3];
    const float* wk    = (const float*)d_in[4];
    const float* gk    = (const float*)d_in[5];
    const float* bk    = (const float*)d_in[6];
    const float* wv    = (const float*)d_in[7];
    const float* gv    = (const float*)d_in[8];
    const float* bv    = (const float*)d_in[9];
    const float* wproj = (const float*)d_in[10];
    const float* bproj = (const float*)d_in[11];
    const float* gp    = (const float*)d_in[12];
    const float* bp    = (const float*)d_in[13];

    float* out  = (float*)d_out;
    float* vout = out + TBD_;

    __half *p_xs, *p_p, *p_wc, *p_wp;
    float *p_ypre, *p_opre;
    float *p_mu, *p_rstd, *p_omu, *p_orstd, *p_part, *p_opart;
    cudaGetSymbolAddress((void**)&p_xs,    g_xs);
    cudaGetSymbolAddress((void**)&p_ypre,  g_ypre);
    cudaGetSymbolAddress((void**)&p_p,     g_p);
    cudaGetSymbolAddress((void**)&p_opre,  g_opre);
    cudaGetSymbolAddress((void**)&p_mu,    g_mu);
    cudaGetSymbolAddress((void**)&p_rstd,  g_rstd);
    cudaGetSymbolAddress((void**)&p_omu,   g_omu);
    cudaGetSymbolAddress((void**)&p_orstd, g_orstd);
    cudaGetSymbolAddress((void**)&p_part,  g_part);
    cudaGetSymbolAddress((void**)&p_opart, g_opart);
    cudaGetSymbolAddress((void**)&p_wc,    g_wc);
    cudaGetSymbolAddress((void**)&p_wp,    g_wp);

    cudaFuncSetAttribute(k_mma_gemm, cudaFuncAttributeMaxDynamicSharedMemorySize,
                         GEMM_SMEM);

    // 0) split fp32 weights into 2 fp16 planes (hi, mid*4096), vec x4
    const int nkb = DH_ * D_;
    k_split2<<<dim3((nkb / 4 + 255) / 256, 3), 256>>>(wq, wk, wv, p_wc, nkb, D_,
                                                      (size_t)DH_ * 1024);
    k_split2<<<dim3((nkb / 4 + 255) / 256, 1), 256>>>(wproj, wproj, wproj, p_wp,
                                                      nkb, DH_, 0);

    // 1) shortcut LIF -> dual-half spikes, vec x4
    k_lif_in<<<BD_ / 1024, 256>>>(x);

    // 2) three branch GEMMs in one launch (z = branch), Keff = 1024, stats fused
    const size_t PSTRIDE = 128ULL * DH_ * 2;
    k_mma_gemm<<<dim3(DH_ / 128, TB_ / 128, 3), 256, GEMM_SMEM>>>(
        p_xs, p_wc, nullptr, p_ypre, p_part,
        DH_, 1024, (size_t)DH_ * 1024, TBDH_, PSTRIDE);

    // 3) finalize BN stats for all 3 branches in one launch
    k_colstats_fin<<<dim3(DH_ / 256, 3), 256>>>(p_part, p_mu, p_rstd, DH_, PSTRIDE);

    // 4) mega-fused BN+LIF(q,k,v) + kv + LIF(0.5) + p
    k_bnlif_kv<<<BD_ / 256, 256>>>(p_ypre, p_mu, p_rstd, gq, bq, gk, bk, gv, bv,
                                   vout, p_p);

    // 5) proj GEMM: Keff = 8192 (+bias), stats fused
    k_mma_gemm<<<dim3(D_ / 128, TB_ / 128, 1), 256, GEMM_SMEM>>>(
        p_p, p_wp, bproj, p_opre, p_opart,
        D_, 8192, 0, 0, 0);

    // 6) finalize proj stats
    k_colstats_fin<<<dim3(D_ / 256, 1), 256>>>(p_opart, p_omu, p_orstd, D_, 0);

    // 7) final BN + residual, vec x4
    k_bn_add<<<TBD_ / 1024, 256>>>(x, gp, bp, out);
}

// round 13
// speedup vs baseline: 1.0878x; 1.0229x over previous
#include <cuda_runtime.h>
#include <cuda_fp16.h>
#include <cstdint>
#include <math.h>

// Shapes (fixed by the problem)
#define T_   4
#define B_   2048
#define D_   512
#define H_   8
#define TB_  8192          // T*B
#define DH_  4096          // D*H
#define BD_  1048576       // B*D
#define TBD_ 4194304       // T*B*D

static const size_t TBDH_ = (size_t)TB_ * DH_;  // 33,554,432

#define SCALE_DN 0.000244140625f   // 2^-12
#define SCALE_UP 4096.0f           // 2^12

// ---------------- scratch (static device globals; no allocation) ------------
__device__ __half g_xs[(size_t)TB_ * 512];           // shortcut spikes (single plane)
__device__ float g_ypre[3ULL * TB_ * DH_];           // pre-BN branch GEMM outputs
__device__ __half g_p[(size_t)TB_ * 4096];           // proj input spikes (single plane)
__device__ float g_opre[(size_t)TB_ * D_];           // pre-BN proj output
__device__ float g_mu[3 * DH_];
__device__ float g_rstd[3 * DH_];
__device__ float g_omu[D_];
__device__ float g_orstd[D_];
__device__ float g_part[3ULL * 128 * DH_ * 2];       // per-rowgroup (128) col partials
__device__ float g_opart[128ULL * D_ * 2];
__device__ __half g_wc[3ULL * DH_ * 1024];           // branch W': [n][hi*2^12 | mid']
__device__ __half g_wp[(size_t)D_ * 8192];           // proj  W': [n][hi*2^12 | mid']

// ======================= PTX helpers =========================================
__device__ __forceinline__ uint32_t smem_u32(const void* p) {
    uint32_t a;
    asm("{ .reg .u64 t; cvta.to.shared.u64 t, %1; cvt.u32.u64 %0, t; }" : "=r"(a) : "l"(p));
    return a;
}
__device__ __forceinline__ void cp16(uint32_t smem, const void* g) {
    asm volatile("cp.async.cg.shared.global [%0], [%1], 16;" :: "r"(smem), "l"(g));
}
#define CP_COMMIT() asm volatile("cp.async.commit_group;" ::: "memory")
#define CP_WAIT0()  asm volatile("cp.async.wait_group 0;" ::: "memory")
#define CP_WAIT1()  asm volatile("cp.async.wait_group 1;" ::: "memory")

__device__ __forceinline__ void ldm_x4(uint32_t* r, uint32_t addr) {
    asm volatile("ldmatrix.sync.aligned.m8n8.x4.shared.b16 {%0,%1,%2,%3}, [%4];"
                 : "=r"(r[0]), "=r"(r[1]), "=r"(r[2]), "=r"(r[3]) : "r"(addr));
}
__device__ __forceinline__ void mma16816(float* d, const uint32_t* a, const uint32_t* b) {
    asm volatile(
        "mma.sync.aligned.m16n8k16.row.col.f32.f16.f16.f32 "
        "{%0,%1,%2,%3}, {%4,%5,%6,%7}, {%8,%9}, {%0,%1,%2,%3};"
        : "+f"(d[0]), "+f"(d[1]), "+f"(d[2]), "+f"(d[3])
        : "r"(a[0]), "r"(a[1]), "r"(a[2]), "r"(a[3]), "r"(b[0]), "r"(b[1]));
}

// ======================= mma.sync fp16 GEMM + fused col stats ================
// C[M,N] = 2^-12 * (A[M,Ka] K-cycled to Keff) x (Bw[N,Keff])^T (+bias), fp32.
// Bw holds [hi*2^12 | mid']. Round-10 tile/layout: CTA 128x128, K-stage 64,
// 128B XOR-swizzled rows, 8 warps (2x4, 64x32), 3-stage cp.async pipeline.
#define STAGE_BYTES 16384   // 128 rows * 128B
#define NSTAGE 3
#define GEMM_SMEM   (2 * NSTAGE * STAGE_BYTES)   // 98304

__global__ __launch_bounds__(256)
void k_mma_gemm(const __half* __restrict__ A,
                const __half* __restrict__ Bw,
                const float* __restrict__ bias,
                float* __restrict__ C,
                float* __restrict__ part,
                int N, int Ka, int Keff,
                size_t strideB, size_t strideC, size_t strideP)
{
    extern __shared__ __align__(128) char smem[];
    const uint32_t sA = smem_u32(smem);
    const uint32_t sB = sA + NSTAGE * STAGE_BYTES;
    const int tid  = threadIdx.x;
    const int wid  = tid >> 5, lane = tid & 31;
    const int wm   = wid >> 2, wn = wid & 3;

    Bw   += (size_t)blockIdx.z * strideB;
    C    += (size_t)blockIdx.z * strideC;
    part += (size_t)blockIdx.z * strideP;

    const __half* Ab = A  + (size_t)blockIdx.y * 128 * (size_t)Ka;
    const __half* Bb = Bw + (size_t)blockIdx.x * 128 * (size_t)Keff;
    const int S = Keff >> 6;

    float acc[4][4][4];
#pragma unroll
    for (int mi = 0; mi < 4; mi++)
#pragma unroll
        for (int ni = 0; ni < 4; ni++)
#pragma unroll
            for (int j = 0; j < 4; j++) acc[mi][ni][j] = 0.f;

    auto load_stage = [&](int s, int buf) {
        int kb  = s << 6;
        int kba = kb & (Ka - 1);               // A K-cycled (Ka power of 2)
        const __half* Ag = Ab + kba;
        const __half* Bg = Bb + kb;
#pragma unroll
        for (int i = 0; i < 4; i++) {
            int q = tid + (i << 8);            // 0..1023 chunk id
            int r = q >> 3, c = q & 7;
            uint32_t off = (uint32_t)r * 128 + (uint32_t)((c ^ (r & 7)) << 4);
            cp16(sA + buf * STAGE_BYTES + off, Ag + (size_t)r * Ka + (c << 3));
            cp16(sB + buf * STAGE_BYTES + off, Bg + (size_t)r * Keff + (c << 3));
        }
    };

    load_stage(0, 0);
    CP_COMMIT();
    if (S > 1) { load_stage(1, 1); CP_COMMIT(); }

    for (int s = 0; s < S; s++) {
        int buf = s % NSTAGE;
        if (s + 1 < S) CP_WAIT1(); else CP_WAIT0();
        __syncthreads();
        if (s + 2 < S) { load_stage(s + 2, (s + 2) % NSTAGE); CP_COMMIT(); }

        uint32_t bA = sA + buf * STAGE_BYTES;
        uint32_t bB = sB + buf * STAGE_BYTES;
#pragma unroll
        for (int kk = 0; kk < 4; kk++) {
            uint32_t afr[4][4];
#pragma unroll
            for (int mi = 0; mi < 4; mi++) {
                int row = wm * 64 + mi * 16 + (lane & 15);
                int c   = (kk << 1) + (lane >> 4);
                ldm_x4(afr[mi], bA + (uint32_t)row * 128 + (uint32_t)((c ^ (row & 7)) << 4));
            }
            uint32_t bfr[4][2];
#pragma unroll
            for (int np = 0; np < 2; np++) {
                int g  = lane >> 3;                       // 0..3
                int nr = wn * 32 + np * 16 + (g >> 1) * 8 + (lane & 7);
                int c  = (kk << 1) + (g & 1);
                uint32_t tmp[4];
                ldm_x4(tmp, bB + (uint32_t)nr * 128 + (uint32_t)((c ^ (nr & 7)) << 4));
                bfr[np * 2 + 0][0] = tmp[0]; bfr[np * 2 + 0][1] = tmp[1];
                bfr[np * 2 + 1][0] = tmp[2]; bfr[np * 2 + 1][1] = tmp[3];
            }
#pragma unroll
            for (int mi = 0; mi < 4; mi++)
#pragma unroll
                for (int ni = 0; ni < 4; ni++)
                    mma16816(acc[mi][ni], afr[mi], bfr[ni]);
        }
        // no bottom sync: buffer reuse distance is 3 stages; top barrier orders.
    }

    // ---------------- epilogue: unscale, bias, store C, fused col stats ----
#pragma unroll
    for (int mi = 0; mi < 4; mi++)
#pragma unroll
        for (int ni = 0; ni < 4; ni++)
#pragma unroll
            for (int j = 0; j < 4; j++) acc[mi][ni][j] *= SCALE_DN;  // exact 2^-12

    int grow = lane >> 2;
    int gcol = (lane & 3) * 2;
    if (bias) {
#pragma unroll
        for (int ni = 0; ni < 4; ni++) {
            int cc = blockIdx.x * 128 + wn * 32 + ni * 8 + gcol;
            float b0 = bias[cc], b1 = bias[cc + 1];
#pragma unroll
            for (int mi = 0; mi < 4; mi++) {
                acc[mi][ni][0] += b0; acc[mi][ni][1] += b1;
                acc[mi][ni][2] += b0; acc[mi][ni][3] += b1;
            }
        }
    }
#pragma unroll
    for (int mi = 0; mi < 4; mi++) {
        int r0 = blockIdx.y * 128 + wm * 64 + mi * 16 + grow;
#pragma unroll
        for (int ni = 0; ni < 4; ni++) {
            int cc = blockIdx.x * 128 + wn * 32 + ni * 8 + gcol;
            *reinterpret_cast<float2*>(C + (size_t)r0 * N + cc) =
                make_float2(acc[mi][ni][0], acc[mi][ni][1]);
            *reinterpret_cast<float2*>(C + (size_t)(r0 + 8) * N + cc) =
                make_float2(acc[mi][ni][2], acc[mi][ni][3]);
        }
    }
    int rowgrp = blockIdx.y * 2 + wm;
#pragma unroll
    for (int ni = 0; ni < 4; ni++) {
#pragma unroll
        for (int jj = 0; jj < 2; jj++) {
            float s = 0.f, q = 0.f;
#pragma unroll
            for (int mi = 0; mi < 4; mi++) {
                float v0 = acc[mi][ni][jj], v1 = acc[mi][ni][jj + 2];
                s += v0 + v1;
                q += v0 * v0 + v1 * v1;
            }
#pragma unroll
            for (int o = 4; o < 32; o <<= 1) {
                s += __shfl_xor_sync(0xffffffffu, s, o);
                q += __shfl_xor_sync(0xffffffffu, q, o);
            }
            if (grow == 0) {
                int cc = blockIdx.x * 128 + wn * 32 + ni * 8 + gcol + jj;
                size_t idx = ((size_t)rowgrp * N + cc) * 2;
                part[idx]     = s;
                part[idx + 1] = q;
            }
        }
    }
}

// ======================= stats finalize (merged over branches via y) =========
__global__ void k_colstats_fin(const float* __restrict__ part,
                               float* __restrict__ mu, float* __restrict__ rstd,
                               int cols, size_t pstride) {
    part += (size_t)blockIdx.y * pstride;
    mu   += (size_t)blockIdx.y * cols;
    rstd += (size_t)blockIdx.y * cols;
    int c = blockIdx.x * 256 + threadIdx.x;
    if (c >= cols) return;
    float s = 0.f, cs = 0.f, q = 0.f, cq = 0.f;
    for (int rg = 0; rg < 128; rg++) {
        float vs = part[((size_t)rg * cols + c) * 2 + 0];
        float vq = part[((size_t)rg * cols + c) * 2 + 1];
        float y1 = vs - cs; float t1 = s + y1; cs = (t1 - s) - y1; s = t1;
        float y2 = vq - cq; float t2 = q + y2; cq = (t2 - q) - y2; q = t2;
    }
    const float invn = 1.0f / 8192.0f;
    float m = s * invn;
    float var = q * invn - m * m;
    mu[c] = m;
    rstd[c] = 1.0f / sqrtf(var + 1e-5f);
}

// ======================= weight split2: [hi*2^12 | mid'], vec x4 =============
__global__ void k_split2(const float* __restrict__ w0, const float* __restrict__ w1,
                         const float* __restrict__ w2, __half* __restrict__ dst,
                         int NK, int K, size_t dstride) {
    int i4 = (blockIdx.x * 256 + threadIdx.x) * 4;
    if (i4 >= NK) return;
    const float* w = (blockIdx.y == 0) ? w0 : (blockIdx.y == 1) ? w1 : w2;
    __half* d = dst + (size_t)blockIdx.y * dstride;
    int n = i4 / K, kk = i4 - n * K;      // 4 consecutive kk (K % 4 == 0)
    float4 v = *reinterpret_cast<const float4*>(w + i4);
    float vv[4] = { v.x, v.y, v.z, v.w };
    __half hs[4], m[4];
#pragma unroll
    for (int j = 0; j < 4; j++) {
        __half h = __float2half_rn(vv[j]);
        float hf = __half2float(h);
        hs[j] = __float2half_rn(hf * SCALE_UP);              // hi*2^12 (exact)
        m[j]  = __float2half_rn((vv[j] - hf) * SCALE_UP);    // mid'
    }
    size_t base = (size_t)n * 2 * K + kk;
    *reinterpret_cast<uint2*>(d + base)     = *reinterpret_cast<uint2*>(hs);
    *reinterpret_cast<uint2*>(d + base + K) = *reinterpret_cast<uint2*>(m);
}

// ======================= elementwise stages ==================================
// shortcut LIF -> single-plane half spikes, 4 elements/thread
__global__ void k_lif_in(const float* __restrict__ x) {
    int i4 = (blockIdx.x * 256 + threadIdx.x) * 4;
    if (i4 >= BD_) return;
    int b = i4 >> 9, d2 = i4 & 511;
    float v[4] = { 0.f, 0.f, 0.f, 0.f };
#pragma unroll
    for (int t = 0; t < T_; t++) {
        float4 xt = *reinterpret_cast<const float4*>(x + t * BD_ + i4);
        float xv[4] = { xt.x, xt.y, xt.z, xt.w };
        __half s[4];
#pragma unroll
        for (int j = 0; j < 4; j++) {
            float dta = xv[j] - v[j];
            v[j] = v[j] + dta * 0.5f;
            float sp = (v[j] - 1.0f) >= 0.0f ? 1.0f : 0.0f;
            s[j] = __float2half(sp);
            v[j] = v[j] * (1.0f - sp);
        }
        size_t base = ((size_t)(t * B_ + b)) * 512 + d2;
        *reinterpret_cast<uint2*>(g_xs + base) = *reinterpret_cast<uint2*>(s);
    }
}

// mega-fused: BN+LIF for q,k,v + kv-sum + kv-LIF(0.5) + p (single plane),
// 128 threads/block (proven best: 3 blocks/SM at ~140 regs)
__global__ __launch_bounds__(128)
void k_bnlif_kv(const float* __restrict__ Y,
                const float* __restrict__ mu, const float* __restrict__ rstd,
                const float* __restrict__ gq, const float* __restrict__ bq,
                const float* __restrict__ gk, const float* __restrict__ bk,
                const float* __restrict__ gv, const float* __restrict__ bv,
                float* __restrict__ vout, __half* __restrict__ P)
{
    int i = blockIdx.x * 128 + threadIdx.x;
    if (i >= BD_) return;
    int b = i >> 9, dd = i & 511;
    int c0 = dd << 3;

    const float* Yb[3] = { Y, Y + TBDH_, Y + 2 * TBDH_ };
    const float* gs[3] = { gq, gk, gv };
    const float* bs[3] = { bq, bk, bv };
    float prm[3][4][8];
#pragma unroll
    for (int br = 0; br < 3; br++)
#pragma unroll
        for (int h = 0; h < 8; h++) {
            prm[br][0][h] = mu[br * DH_ + c0 + h];
            prm[br][1][h] = rstd[br * DH_ + c0 + h];
            prm[br][2][h] = gs[br][c0 + h];
            prm[br][3][h] = bs[br][c0 + h];
        }

    float uq[8], uk[8], uv[8], ukv = 0.f;
#pragma unroll
    for (int h = 0; h < 8; h++) { uq[h] = uk[h] = uv[h] = 0.f; }

#pragma unroll
    for (int t = 0; t < T_; t++) {
        int row = t * B_ + b;
        size_t rb = (size_t)row * DH_ + c0;
        float xq[8], xk[8], xv[8];
        *reinterpret_cast<float4*>(&xq[0]) = *reinterpret_cast<const float4*>(Yb[0] + rb);
        *reinterpret_cast<float4*>(&xq[4]) = *reinterpret_cast<const float4*>(Yb[0] + rb + 4);
        *reinterpret_cast<float4*>(&xk[0]) = *reinterpret_cast<const float4*>(Yb[1] + rb);
        *reinterpret_cast<float4*>(&xk[4]) = *reinterpret_cast<const float4*>(Yb[1] + rb + 4);
        *reinterpret_cast<float4*>(&xv[0]) = *reinterpret_cast<const float4*>(Yb[2] + rb);
        *reinterpret_cast<float4*>(&xv[4]) = *reinterpret_cast<const float4*>(Yb[2] + rb + 4);

        float sq[8];
        float kv = 0.f;
        size_t ob = (size_t)row * DH_ + dd;
#pragma unroll
        for (int h = 0; h < 8; h++) {
            float y = prm[0][2][h] * (xq[h] - prm[0][0][h]); y *= prm[0][1][h]; y += prm[0][3][h];
            float d = y - uq[h]; uq[h] = uq[h] + d * 0.5f;
            float s = (uq[h] - 1.0f) >= 0.f ? 1.f : 0.f; sq[h] = s; uq[h] *= (1.f - s);
            y = prm[1][2][h] * (xk[h] - prm[1][0][h]); y *= prm[1][1][h]; y += prm[1][3][h];
            d = y - uk[h]; uk[h] = uk[h] + d * 0.5f;
            float sk = (uk[h] - 1.0f) >= 0.f ? 1.f : 0.f; uk[h] *= (1.f - sk);
            y = prm[2][2][h] * (xv[h] - prm[2][0][h]); y *= prm[2][1][h]; y += prm[2][3][h];
            d = y - uv[h]; uv[h] = uv[h] + d * 0.5f;
            float sv = (uv[h] - 1.0f) >= 0.f ? 1.f : 0.f; uv[h] *= (1.f - sv);

            vout[ob + (h << 9)] = sv;
            kv += sk * sv;
        }
        float d2 = kv - ukv; ukv = ukv + d2 * 0.5f;
        float skv = (ukv - 0.5f) >= 0.f ? 1.f : 0.f; ukv *= (1.f - skv);

        size_t pb = (size_t)row * 4096 + dd;
#pragma unroll
        for (int h = 0; h < 8; h++)
            P[pb + (h << 9)] = __float2half(sq[h] * skv);
    }
}

// final BN + residual, 4 elements/thread
__global__ void k_bn_add(const float* __restrict__ x, const float* __restrict__ gp,
                         const float* __restrict__ bp, float* __restrict__ out) {
    int i4 = (blockIdx.x * 256 + threadIdx.x) * 4;
    if (i4 >= TBD_) return;
    int c = i4 & 511;
    float4 v  = *reinterpret_cast<const float4*>(g_opre + i4);
    float4 xr = *reinterpret_cast<const float4*>(x + i4);
    float4 mg = *reinterpret_cast<const float4*>(g_omu + c);
    float4 rg = *reinterpret_cast<const float4*>(g_orstd + c);
    float4 gg = *reinterpret_cast<const float4*>(gp + c);
    float4 bb = *reinterpret_cast<const float4*>(bp + c);
    float vv[4] = { v.x, v.y, v.z, v.w };
    float xx[4] = { xr.x, xr.y, xr.z, xr.w };
    float mm[4] = { mg.x, mg.y, mg.z, mg.w };
    float rr[4] = { rg.x, rg.y, rg.z, rg.w };
    float ga[4] = { gg.x, gg.y, gg.z, gg.w };
    float ba[4] = { bb.x, bb.y, bb.z, bb.w };
    float o[4];
#pragma unroll
    for (int j = 0; j < 4; j++) {
        float y = ga[j] * (vv[j] - mm[j]);
        y = y * rr[j];
        y = y + ba[j];
        o[j] = y + xx[j];
    }
    *reinterpret_cast<float4*>(out + i4) =
        make_float4(o[0], o[1], o[2], o[3]);
}

// ======================= launch ==============================================
extern "C" void kernel_launch(void* const* d_in, const int* in_sizes, int n_in,
                              void* d_out, int out_size) {
    const float* x     = (const float*)d_in[0];
    const float* wq    = (const float*)d_in[1];
    const float* gq    = (const float*)d_in[2];
    const float* bq    = (const float*)d_in[3];
    const float* wk    = (const float*)d_in[4];
    const float* gk    = (const float*)d_in[5];
    const float* bk    = (const float*)d_in[6];
    const float* wv    = (const float*)d_in[7];
    const float* gv    = (const float*)d_in[8];
    const float* bv    = (const float*)d_in[9];
    const float* wproj = (const float*)d_in[10];
    const float* bproj = (const float*)d_in[11];
    const float* gp    = (const float*)d_in[12];
    const float* bp    = (const float*)d_in[13];

    float* out  = (float*)d_out;
    float* vout = out + TBD_;

    __half *p_xs, *p_p, *p_wc, *p_wp;
    float *p_ypre, *p_opre;
    float *p_mu, *p_rstd, *p_omu, *p_orstd, *p_part, *p_opart;
    cudaGetSymbolAddress((void**)&p_xs,    g_xs);
    cudaGetSymbolAddress((void**)&p_ypre,  g_ypre);
    cudaGetSymbolAddress((void**)&p_p,     g_p);
    cudaGetSymbolAddress((void**)&p_opre,  g_opre);
    cudaGetSymbolAddress((void**)&p_mu,    g_mu);
    cudaGetSymbolAddress((void**)&p_rstd,  g_rstd);
    cudaGetSymbolAddress((void**)&p_omu,   g_omu);
    cudaGetSymbolAddress((void**)&p_orstd, g_orstd);
    cudaGetSymbolAddress((void**)&p_part,  g_part);
    cudaGetSymbolAddress((void**)&p_opart, g_opart);
    cudaGetSymbolAddress((void**)&p_wc,    g_wc);
    cudaGetSymbolAddress((void**)&p_wp,    g_wp);

    cudaFuncSetAttribute(k_mma_gemm, cudaFuncAttributeMaxDynamicSharedMemorySize,
                         GEMM_SMEM);

    // 0) split fp32 weights into [hi*2^12 | mid'] fp16 planes, vec x4
    const int nkb = DH_ * D_;
    k_split2<<<dim3((nkb / 4 + 255) / 256, 3), 256>>>(wq, wk, wv, p_wc, nkb, D_,
                                                      (size_t)DH_ * 1024);
    k_split2<<<dim3((nkb / 4 + 255) / 256, 1), 256>>>(wproj, wproj, wproj, p_wp,
                                                      nkb, DH_, 0);

    // 1) shortcut LIF -> single-plane half spikes, vec x4
    k_lif_in<<<BD_ / 1024, 256>>>(x);

    // 2) three branch GEMMs in one launch (z = branch), Ka=512 cycled to 1024
    const size_t PSTRIDE = 128ULL * DH_ * 2;
    k_mma_gemm<<<dim3(DH_ / 128, TB_ / 128, 3), 256, GEMM_SMEM>>>(
        p_xs, p_wc, nullptr, p_ypre, p_part,
        DH_, 512, 1024, (size_t)DH_ * 1024, TBDH_, PSTRIDE);

    // 3) finalize BN stats for all 3 branches in one launch
    k_colstats_fin<<<dim3(DH_ / 256, 3), 256>>>(p_part, p_mu, p_rstd, DH_, PSTRIDE);

    // 4) mega-fused BN+LIF(q,k,v) + kv + LIF(0.5) + p (128 thr/blk)
    k_bnlif_kv<<<BD_ / 128, 128>>>(p_ypre, p_mu, p_rstd, gq, bq, gk, bk, gv, bv,
                                   vout, p_p);

    // 5) proj GEMM: Ka=4096 cycled to 8192 (+bias), stats fused
    k_mma_gemm<<<dim3(D_ / 128, TB_ / 128, 1), 256, GEMM_SMEM>>>(
        p_p, p_wp, bproj, p_opre, p_opart,
        D_, 4096, 8192, 0, 0, 0);

    // 6) finalize proj stats
    k_colstats_fin<<<dim3(D_ / 256, 1), 256>>>(p_opart, p_omu, p_orstd, D_, 0);

    // 7) final BN + residual, vec x4
    k_bn_add<<<TBD_ / 1024, 256>>>(x, gp, bp, out);
}

// round 15
// speedup vs baseline: 1.1226x; 1.0320x over previous
#include <cuda_runtime.h>
#include <cuda_fp16.h>
#include <cstdint>
#include <math.h>

// Shapes (fixed by the problem)
#define T_   4
#define B_   2048
#define D_   512
#define H_   8
#define TB_  8192          // T*B
#define DH_  4096          // D*H
#define BD_  1048576       // B*D
#define TBD_ 4194304       // T*B*D

static const size_t TBDH_ = (size_t)TB_ * DH_;  // 33,554,432

#define SCALE_DN 0.000244140625f   // 2^-12
#define SCALE_UP 4096.0f           // 2^12

// ---------------- scratch (static device globals; no allocation) ------------
__device__ __half g_xs[(size_t)TB_ * 1024];          // shortcut spikes dual-half [s | s*2^-12]
__device__ float g_ypre[3ULL * TB_ * DH_];           // pre-BN branch GEMM outputs
__device__ __half g_p[(size_t)TB_ * 4096];           // proj input spikes (single plane)
__device__ float g_opre[(size_t)TB_ * D_];           // pre-BN proj output
__device__ float g_mu[3 * DH_];
__device__ float g_rstd[3 * DH_];
__device__ float g_omu[D_];
__device__ float g_orstd[D_];
__device__ float g_part[3ULL * 128 * DH_ * 2];       // per-rowgroup (128) col partials
__device__ float g_opart[128ULL * D_ * 2];
__device__ __half g_wc[3ULL * DH_ * 1024];           // branch weights [hi | mid*2^12]
__device__ __half g_wp[(size_t)D_ * 8192];           // proj weights [hi*2^12 | mid']

// ======================= PTX helpers =========================================
__device__ __forceinline__ uint32_t smem_u32(const void* p) {
    uint32_t a;
    asm("{ .reg .u64 t; cvta.to.shared.u64 t, %1; cvt.u32.u64 %0, t; }" : "=r"(a) : "l"(p));
    return a;
}
__device__ __forceinline__ void cp16(uint32_t smem, const void* g) {
    asm volatile("cp.async.cg.shared.global [%0], [%1], 16;" :: "r"(smem), "l"(g));
}
#define CP_COMMIT() asm volatile("cp.async.commit_group;" ::: "memory")
#define CP_WAIT0()  asm volatile("cp.async.wait_group 0;" ::: "memory")
#define CP_WAIT1()  asm volatile("cp.async.wait_group 1;" ::: "memory")

__device__ __forceinline__ void ldm_x4(uint32_t* r, uint32_t addr) {
    asm volatile("ldmatrix.sync.aligned.m8n8.x4.shared.b16 {%0,%1,%2,%3}, [%4];"
                 : "=r"(r[0]), "=r"(r[1]), "=r"(r[2]), "=r"(r[3]) : "r"(addr));
}
__device__ __forceinline__ void mma16816(float* d, const uint32_t* a, const uint32_t* b) {
    asm volatile(
        "mma.sync.aligned.m16n8k16.row.col.f32.f16.f16.f32 "
        "{%0,%1,%2,%3}, {%4,%5,%6,%7}, {%8,%9}, {%0,%1,%2,%3};"
        : "+f"(d[0]), "+f"(d[1]), "+f"(d[2]), "+f"(d[3])
        : "r"(a[0]), "r"(a[1]), "r"(a[2]), "r"(a[3]), "r"(b[0]), "r"(b[1]));
}

// ======================= mma.sync fp16 GEMM + fused col stats ================
// Template: CYCLE_A -> A index masked by (Ka-1) (A K-cycled single plane);
//           SCALE_OUT -> epilogue multiplies acc by 2^-12 (exact).
// CTA tile 128x128, K-stage 64 (128B XOR-swizzled rows), 8 warps (2x4, 64x32),
// 3-stage cp.async pipeline.  (Round-10 proven configuration.)
#define STAGE_BYTES 16384   // 128 rows * 128B
#define NSTAGE 3
#define GEMM_SMEM   (2 * NSTAGE * STAGE_BYTES)   // 98304

template<bool CYCLE_A, bool SCALE_OUT>
__global__ __launch_bounds__(256)
void k_mma_gemm(const __half* __restrict__ A,
                const __half* __restrict__ Bw,
                const float* __restrict__ bias,
                float* __restrict__ C,
                float* __restrict__ part,
                int N, int Ka, int Keff,
                size_t strideB, size_t strideC, size_t strideP)
{
    extern __shared__ __align__(128) char smem[];
    const uint32_t sA = smem_u32(smem);
    const uint32_t sB = sA + NSTAGE * STAGE_BYTES;
    const int tid  = threadIdx.x;
    const int wid  = tid >> 5, lane = tid & 31;
    const int wm   = wid >> 2, wn = wid & 3;

    Bw   += (size_t)blockIdx.z * strideB;
    C    += (size_t)blockIdx.z * strideC;
    part += (size_t)blockIdx.z * strideP;

    const int KaRow = CYCLE_A ? Ka : Keff;     // A row pitch
    const __half* Ab = A  + (size_t)blockIdx.y * 128 * (size_t)KaRow;
    const __half* Bb = Bw + (size_t)blockIdx.x * 128 * (size_t)Keff;
    const int S = Keff >> 6;

    float acc[4][4][4];
#pragma unroll
    for (int mi = 0; mi < 4; mi++)
#pragma unroll
        for (int ni = 0; ni < 4; ni++)
#pragma unroll
            for (int j = 0; j < 4; j++) acc[mi][ni][j] = 0.f;

    auto load_stage = [&](int s, int buf) {
        int kb  = s << 6;
        int kba = CYCLE_A ? (kb & (Ka - 1)) : kb;
        const __half* Ag = Ab + kba;
        const __half* Bg = Bb + kb;
#pragma unroll
        for (int i = 0; i < 4; i++) {
            int q = tid + (i << 8);            // 0..1023 chunk id
            int r = q >> 3, c = q & 7;
            uint32_t off = (uint32_t)r * 128 + (uint32_t)((c ^ (r & 7)) << 4);
            cp16(sA + buf * STAGE_BYTES + off, Ag + (size_t)r * KaRow + (c << 3));
            cp16(sB + buf * STAGE_BYTES + off, Bg + (size_t)r * Keff + (c << 3));
        }
    };

    load_stage(0, 0);
    CP_COMMIT();
    if (S > 1) { load_stage(1, 1); CP_COMMIT(); }

    for (int s = 0; s < S; s++) {
        int buf = s % NSTAGE;
        if (s + 1 < S) CP_WAIT1(); else CP_WAIT0();
        __syncthreads();
        if (s + 2 < S) { load_stage(s + 2, (s + 2) % NSTAGE); CP_COMMIT(); }

        uint32_t bA = sA + buf * STAGE_BYTES;
        uint32_t bB = sB + buf * STAGE_BYTES;
#pragma unroll
        for (int kk = 0; kk < 4; kk++) {
            uint32_t afr[4][4];
#pragma unroll
            for (int mi = 0; mi < 4; mi++) {
                int row = wm * 64 + mi * 16 + (lane & 15);
                int c   = (kk << 1) + (lane >> 4);
                ldm_x4(afr[mi], bA + (uint32_t)row * 128 + (uint32_t)((c ^ (row & 7)) << 4));
            }
            uint32_t bfr[4][2];
#pragma unroll
            for (int np = 0; np < 2; np++) {
                int g  = lane >> 3;                       // 0..3
                int nr = wn * 32 + np * 16 + (g >> 1) * 8 + (lane & 7);
                int c  = (kk << 1) + (g & 1);
                uint32_t tmp[4];
                ldm_x4(tmp, bB + (uint32_t)nr * 128 + (uint32_t)((c ^ (nr & 7)) << 4));
                bfr[np * 2 + 0][0] = tmp[0]; bfr[np * 2 + 0][1] = tmp[1];
                bfr[np * 2 + 1][0] = tmp[2]; bfr[np * 2 + 1][1] = tmp[3];
            }
#pragma unroll
            for (int mi = 0; mi < 4; mi++)
#pragma unroll
                for (int ni = 0; ni < 4; ni++)
                    mma16816(acc[mi][ni], afr[mi], bfr[ni]);
        }
        // no bottom sync: buffer reuse distance is 3 stages; top barrier orders.
    }

    // ---------------- epilogue: (unscale,) bias, store C, fused col stats ---
    if (SCALE_OUT) {
#pragma unroll
        for (int mi = 0; mi < 4; mi++)
#pragma unroll
            for (int ni = 0; ni < 4; ni++)
#pragma unroll
                for (int j = 0; j < 4; j++) acc[mi][ni][j] *= SCALE_DN;  // exact
    }
    int grow = lane >> 2;
    int gcol = (lane & 3) * 2;
    if (bias) {
#pragma unroll
        for (int ni = 0; ni < 4; ni++) {
            int cc = blockIdx.x * 128 + wn * 32 + ni * 8 + gcol;
            float b0 = bias[cc], b1 = bias[cc + 1];
#pragma unroll
            for (int mi = 0; mi < 4; mi++) {
                acc[mi][ni][0] += b0; acc[mi][ni][1] += b1;
                acc[mi][ni][2] += b0; acc[mi][ni][3] += b1;
            }
        }
    }
#pragma unroll
    for (int mi = 0; mi < 4; mi++) {
        int r0 = blockIdx.y * 128 + wm * 64 + mi * 16 + grow;
#pragma unroll
        for (int ni = 0; ni < 4; ni++) {
            int cc = blockIdx.x * 128 + wn * 32 + ni * 8 + gcol;
            *reinterpret_cast<float2*>(C + (size_t)r0 * N + cc) =
                make_float2(acc[mi][ni][0], acc[mi][ni][1]);
            *reinterpret_cast<float2*>(C + (size_t)(r0 + 8) * N + cc) =
                make_float2(acc[mi][ni][2], acc[mi][ni][3]);
        }
    }
    int rowgrp = blockIdx.y * 2 + wm;
#pragma unroll
    for (int ni = 0; ni < 4; ni++) {
#pragma unroll
        for (int jj = 0; jj < 2; jj++) {
            float s = 0.f, q = 0.f;
#pragma unroll
            for (int mi = 0; mi < 4; mi++) {
                float v0 = acc[mi][ni][jj], v1 = acc[mi][ni][jj + 2];
                s += v0 + v1;
                q += v0 * v0 + v1 * v1;
            }
#pragma unroll
            for (int o = 4; o < 32; o <<= 1) {
                s += __shfl_xor_sync(0xffffffffu, s, o);
                q += __shfl_xor_sync(0xffffffffu, q, o);
            }
            if (grow == 0) {
                int cc = blockIdx.x * 128 + wn * 32 + ni * 8 + gcol + jj;
                size_t idx = ((size_t)rowgrp * N + cc) * 2;
                part[idx]     = s;
                part[idx + 1] = q;
            }
        }
    }
}

// ======================= stats finalize (merged over branches via y) =========
__global__ void k_colstats_fin(const float* __restrict__ part,
                               float* __restrict__ mu, float* __restrict__ rstd,
                               int cols, size_t pstride) {
    part += (size_t)blockIdx.y * pstride;
    mu   += (size_t)blockIdx.y * cols;
    rstd += (size_t)blockIdx.y * cols;
    int c = blockIdx.x * 256 + threadIdx.x;
    if (c >= cols) return;
    float s = 0.f, cs = 0.f, q = 0.f, cq = 0.f;
    for (int rg = 0; rg < 128; rg++) {
        float vs = part[((size_t)rg * cols + c) * 2 + 0];
        float vq = part[((size_t)rg * cols + c) * 2 + 1];
        float y1 = vs - cs; float t1 = s + y1; cs = (t1 - s) - y1; s = t1;
        float y2 = vq - cq; float t2 = q + y2; cq = (t2 - q) - y2; q = t2;
    }
    const float invn = 1.0f / 8192.0f;
    float m = s * invn;
    float var = q * invn - m * m;
    mu[c] = m;
    rstd[c] = 1.0f / sqrtf(var + 1e-5f);
}

// ======================= weight splits, vec x4 ===============================
// Branch (round-10): [hi | mid*2^12]
__global__ void k_split2(const float* __restrict__ w0, const float* __restrict__ w1,
                         const float* __restrict__ w2, __half* __restrict__ dst,
                         int NK, int K, size_t dstride) {
    int i4 = (blockIdx.x * 256 + threadIdx.x) * 4;
    if (i4 >= NK) return;
    const float* w = (blockIdx.y == 0) ? w0 : (blockIdx.y == 1) ? w1 : w2;
    __half* d = dst + (size_t)blockIdx.y * dstride;
    int n = i4 / K, kk = i4 - n * K;
    float4 v = *reinterpret_cast<const float4*>(w + i4);
    float vv[4] = { v.x, v.y, v.z, v.w };
    __half h[4], m[4];
#pragma unroll
    for (int j = 0; j < 4; j++) {
        h[j] = __float2half_rn(vv[j]);
        float r1 = vv[j] - __half2float(h[j]);
        m[j] = __float2half_rn(r1 * SCALE_UP);
    }
    size_t base = (size_t)n * 2 * K + kk;
    *reinterpret_cast<uint2*>(d + base)     = *reinterpret_cast<uint2*>(h);
    *reinterpret_cast<uint2*>(d + base + K) = *reinterpret_cast<uint2*>(m);
}

// Proj (folded): [hi*2^12 | mid']
__global__ void k_split2_fold(const float* __restrict__ w, __half* __restrict__ d,
                              int NK, int K) {
    int i4 = (blockIdx.x * 256 + threadIdx.x) * 4;
    if (i4 >= NK) return;
    int n = i4 / K, kk = i4 - n * K;
    float4 v = *reinterpret_cast<const float4*>(w + i4);
    float vv[4] = { v.x, v.y, v.z, v.w };
    __half hs[4], m[4];
#pragma unroll
    for (int j = 0; j < 4; j++) {
        __half h = __float2half_rn(vv[j]);
        float hf = __half2float(h);
        hs[j] = __float2half_rn(hf * SCALE_UP);              // hi*2^12 (exact)
        m[j]  = __float2half_rn((vv[j] - hf) * SCALE_UP);    // mid'
    }
    size_t base = (size_t)n * 2 * K + kk;
    *reinterpret_cast<uint2*>(d + base)     = *reinterpret_cast<uint2*>(hs);
    *reinterpret_cast<uint2*>(d + base + K) = *reinterpret_cast<uint2*>(m);
}

// ======================= elementwise stages ==================================
// shortcut LIF -> dual-half spikes [s | s*2^-12], vec x4 (round-10)
__global__ void k_lif_in(const float* __restrict__ x) {
    int i4 = (blockIdx.x * 256 + threadIdx.x) * 4;
    if (i4 >= BD_) return;
    int b = i4 >> 9, d2 = i4 & 511;
    float v[4] = { 0.f, 0.f, 0.f, 0.f };
#pragma unroll
    for (int t = 0; t < T_; t++) {
        float4 xt = *reinterpret_cast<const float4*>(x + t * BD_ + i4);
        float xv[4] = { xt.x, xt.y, xt.z, xt.w };
        __half s[4], sd[4];
#pragma unroll
        for (int j = 0; j < 4; j++) {
            float dta = xv[j] - v[j];
            v[j] = v[j] + dta * 0.5f;
            float sp = (v[j] - 1.0f) >= 0.0f ? 1.0f : 0.0f;
            s[j]  = __float2half(sp);
            sd[j] = __float2half(sp * SCALE_DN);
            v[j] = v[j] * (1.0f - sp);
        }
        size_t base = ((size_t)(t * B_ + b)) * 1024 + d2;
        *reinterpret_cast<uint2*>(g_xs + base)       = *reinterpret_cast<uint2*>(s);
        *reinterpret_cast<uint2*>(g_xs + base + 512) = *reinterpret_cast<uint2*>(sd);
    }
}

// mega-fused: BN+LIF for q,k,v + kv-sum + kv-LIF(0.5) + p (single plane),
// 128 threads/block (proven best: 3 blocks/SM)
__global__ __launch_bounds__(128)
void k_bnlif_kv(const float* __restrict__ Y,
                const float* __restrict__ mu, const float* __restrict__ rstd,
                const float* __restrict__ gq, const float* __restrict__ bq,
                const float* __restrict__ gk, const float* __restrict__ bk,
                const float* __restrict__ gv, const float* __restrict__ bv,
                float* __restrict__ vout, __half* __restrict__ P)
{
    int i = blockIdx.x * 128 + threadIdx.x;
    if (i >= BD_) return;
    int b = i >> 9, dd = i & 511;
    int c0 = dd << 3;

    const float* Yb[3] = { Y, Y + TBDH_, Y + 2 * TBDH_ };
    const float* gs[3] = { gq, gk, gv };
    const float* bs[3] = { bq, bk, bv };
    float prm[3][4][8];
#pragma unroll
    for (int br = 0; br < 3; br++)
#pragma unroll
        for (int h = 0; h < 8; h++) {
            prm[br][0][h] = mu[br * DH_ + c0 + h];
            prm[br][1][h] = rstd[br * DH_ + c0 + h];
            prm[br][2][h] = gs[br][c0 + h];
            prm[br][3][h] = bs[br][c0 + h];
        }

    float uq[8], uk[8], uv[8], ukv = 0.f;
#pragma unroll
    for (int h = 0; h < 8; h++) { uq[h] = uk[h] = uv[h] = 0.f; }

#pragma unroll
    for (int t = 0; t < T_; t++) {
        int row = t * B_ + b;
        size_t rb = (size_t)row * DH_ + c0;
        float xq[8], xk[8], xv[8];
        *reinterpret_cast<float4*>(&xq[0]) = *reinterpret_cast<const float4*>(Yb[0] + rb);
        *reinterpret_cast<float4*>(&xq[4]) = *reinterpret_cast<const float4*>(Yb[0] + rb + 4);
        *reinterpret_cast<float4*>(&xk[0]) = *reinterpret_cast<const float4*>(Yb[1] + rb);
        *reinterpret_cast<float4*>(&xk[4]) = *reinterpret_cast<const float4*>(Yb[1] + rb + 4);
        *reinterpret_cast<float4*>(&xv[0]) = *reinterpret_cast<const float4*>(Yb[2] + rb);
        *reinterpret_cast<float4*>(&xv[4]) = *reinterpret_cast<const float4*>(Yb[2] + rb + 4);

        float sq[8];
        float kv = 0.f;
        size_t ob = (size_t)row * DH_ + dd;
#pragma unroll
        for (int h = 0; h < 8; h++) {
            float y = prm[0][2][h] * (xq[h] - prm[0][0][h]); y *= prm[0][1][h]; y += prm[0][3][h];
            float d = y - uq[h]; uq[h] = uq[h] + d * 0.5f;
            float s = (uq[h] - 1.0f) >= 0.f ? 1.f : 0.f; sq[h] = s; uq[h] *= (1.f - s);
            y = prm[1][2][h] * (xk[h] - prm[1][0][h]); y *= prm[1][1][h]; y += prm[1][3][h];
            d = y - uk[h]; uk[h] = uk[h] + d * 0.5f;
            float sk = (uk[h] - 1.0f) >= 0.f ? 1.f : 0.f; uk[h] *= (1.f - sk);
            y = prm[2][2][h] * (xv[h] - prm[2][0][h]); y *= prm[2][1][h]; y += prm[2][3][h];
            d = y - uv[h]; uv[h] = uv[h] + d * 0.5f;
            float sv = (uv[h] - 1.0f) >= 0.f ? 1.f : 0.f; uv[h] *= (1.f - sv);

            vout[ob + (h << 9)] = sv;
            kv += sk * sv;
        }
        float d2 = kv - ukv; ukv = ukv + d2 * 0.5f;
        float skv = (ukv - 0.5f) >= 0.f ? 1.f : 0.f; ukv *= (1.f - skv);

        size_t pb = (size_t)row * 4096 + dd;
#pragma unroll
        for (int h = 0; h < 8; h++)
            P[pb + (h << 9)] = __float2half(sq[h] * skv);
    }
}

// final BN + residual, 4 elements/thread
__global__ void k_bn_add(const float* __restrict__ x, const float* __restrict__ gp,
                         const float* __restrict__ bp, float* __restrict__ out) {
    int i4 = (blockIdx.x * 256 + threadIdx.x) * 4;
    if (i4 >= TBD_) return;
    int c = i4 & 511;
    float4 v  = *reinterpret_cast<const float4*>(g_opre + i4);
    float4 xr = *reinterpret_cast<const float4*>(x + i4);
    float4 mg = *reinterpret_cast<const float4*>(g_omu + c);
    float4 rg = *reinterpret_cast<const float4*>(g_orstd + c);
    float4 gg = *reinterpret_cast<const float4*>(gp + c);
    float4 bb = *reinterpret_cast<const float4*>(bp + c);
    float vv[4] = { v.x, v.y, v.z, v.w };
    float xx[4] = { xr.x, xr.y, xr.z, xr.w };
    float mm[4] = { mg.x, mg.y, mg.z, mg.w };
    float rr[4] = { rg.x, rg.y, rg.z, rg.w };
    float ga[4] = { gg.x, gg.y, gg.z, gg.w };
    float ba[4] = { bb.x, bb.y, bb.z, bb.w };
    float o[4];
#pragma unroll
    for (int j = 0; j < 4; j++) {
        float y = ga[j] * (vv[j] - mm[j]);
        y = y * rr[j];
        y = y + ba[j];
        o[j] = y + xx[j];
    }
    *reinterpret_cast<float4*>(out + i4) =
        make_float4(o[0], o[1], o[2], o[3]);
}

// ======================= launch ==============================================
extern "C" void kernel_launch(void* const* d_in, const int* in_sizes, int n_in,
                              void* d_out, int out_size) {
    const float* x     = (const float*)d_in[0];
    const float* wq    = (const float*)d_in[1];
    const float* gq    = (const float*)d_in[2];
    const float* bq    = (const float*)d_in[3];
    const float* wk    = (const float*)d_in[4];
    const float* gk    = (const float*)d_in[5];
    const float* bk    = (const float*)d_in[6];
    const float* wv    = (const float*)d_in[7];
    const float* gv    = (const float*)d_in[8];
    const float* bv    = (const float*)d_in[9];
    const float* wproj = (const float*)d_in[10];
    const float* bproj = (const float*)d_in[11];
    const float* gp    = (const float*)d_in[12];
    const float* bp    = (const float*)d_in[13];

    float* out  = (float*)d_out;
    float* vout = out + TBD_;

    __half *p_xs, *p_p, *p_wc, *p_wp;
    float *p_ypre, *p_opre;
    float *p_mu, *p_rstd, *p_omu, *p_orstd, *p_part, *p_opart;
    cudaGetSymbolAddress((void**)&p_xs,    g_xs);
    cudaGetSymbolAddress((void**)&p_ypre,  g_ypre);
    cudaGetSymbolAddress((void**)&p_p,     g_p);
    cudaGetSymbolAddress((void**)&p_opre,  g_opre);
    cudaGetSymbolAddress((void**)&p_mu,    g_mu);
    cudaGetSymbolAddress((void**)&p_rstd,  g_rstd);
    cudaGetSymbolAddress((void**)&p_omu,   g_omu);
    cudaGetSymbolAddress((void**)&p_orstd, g_orstd);
    cudaGetSymbolAddress((void**)&p_part,  g_part);
    cudaGetSymbolAddress((void**)&p_opart, g_opart);
    cudaGetSymbolAddress((void**)&p_wc,    g_wc);
    cudaGetSymbolAddress((void**)&p_wp,    g_wp);

    cudaFuncSetAttribute(k_mma_gemm<false, false>,
                         cudaFuncAttributeMaxDynamicSharedMemorySize, GEMM_SMEM);
    cudaFuncSetAttribute(k_mma_gemm<true, true>,
                         cudaFuncAttributeMaxDynamicSharedMemorySize, GEMM_SMEM);

    // 0) weight splits: branch [hi | mid*2^12]; proj folded [hi*2^12 | mid']
    const int nkb = DH_ * D_;
    k_split2<<<dim3((nkb / 4 + 255) / 256, 3), 256>>>(wq, wk, wv, p_wc, nkb, D_,
                                                      (size_t)DH_ * 1024);
    k_split2_fold<<<(nkb / 4 + 255) / 256, 256>>>(wproj, p_wp, nkb, DH_);

    // 1) shortcut LIF -> dual-half spikes, vec x4
    k_lif_in<<<BD_ / 1024, 256>>>(x);

    // 2) three branch GEMMs in one launch (z = branch), Keff = 1024 contiguous
    const size_t PSTRIDE = 128ULL * DH_ * 2;
    k_mma_gemm<false, false><<<dim3(DH_ / 128, TB_ / 128, 3), 256, GEMM_SMEM>>>(
        p_xs, p_wc, nullptr, p_ypre, p_part,
        DH_, 1024, 1024, (size_t)DH_ * 1024, TBDH_, PSTRIDE);

    // 3) finalize BN stats for all 3 branches in one launch
    k_colstats_fin<<<dim3(DH_ / 256, 3), 256>>>(p_part, p_mu, p_rstd, DH_, PSTRIDE);

    // 4) mega-fused BN+LIF(q,k,v) + kv + LIF(0.5) + p (single plane, 128 thr)
    k_bnlif_kv<<<BD_ / 128, 128>>>(p_ypre, p_mu, p_rstd, gq, bq, gk, bk, gv, bv,
                                   vout, p_p);

    // 5) proj GEMM: single-plane A K-cycled 4096->8192 (+bias), epilogue 2^-12
    k_mma_gemm<true, true><<<dim3(D_ / 128, TB_ / 128, 1), 256, GEMM_SMEM>>>(
        p_p, p_wp, bproj, p_opre, p_opart,
        D_, 4096, 8192, 0, 0, 0);

    // 6) finalize proj stats
    k_colstats_fin<<<dim3(D_ / 256, 1), 256>>>(p_opart, p_omu, p_orstd, D_, 0);

    // 7) final BN + residual, vec x4
    k_bn_add<<<TBD_ / 1024, 256>>>(x, gp, bp, out);
}

// round 16
// speedup vs baseline: 1.1501x; 1.0244x over previous
#include <cuda_runtime.h>
#include <cuda_fp16.h>
#include <cstdint>
#include <math.h>

// Shapes (fixed by the problem)
#define T_   4
#define B_   2048
#define D_   512
#define H_   8
#define TB_  8192          // T*B
#define DH_  4096          // D*H
#define BD_  1048576       // B*D
#define TBD_ 4194304       // T*B*D

static const size_t TBDH_ = (size_t)TB_ * DH_;  // 33,554,432

#define SCALE_DN 0.000244140625f   // 2^-12
#define SCALE_UP 4096.0f           // 2^12

// ---------------- scratch (static device globals; no allocation) ------------
__device__ __half g_xs[(size_t)TB_ * 1024];          // shortcut spikes dual-half [s | s*2^-12]
__device__ float g_ypre[3ULL * TB_ * DH_];           // pre-BN branch GEMM outputs
__device__ __half g_p[(size_t)TB_ * 4096];           // proj input spikes (single plane)
__device__ float g_opre[(size_t)TB_ * D_];           // pre-BN proj output
__device__ float g_mu[3 * DH_];
__device__ float g_rstd[3 * DH_];
__device__ float g_omu[D_];
__device__ float g_orstd[D_];
__device__ float g_part[3ULL * 128 * DH_ * 2];       // per-rowgroup (128) col partials
__device__ float g_opart[128ULL * D_ * 2];
__device__ __half g_wc[3ULL * DH_ * 1024];           // branch weights [hi | mid*2^12]
__device__ __half g_wp[(size_t)D_ * 8192];           // proj weights [hi*2^12 | mid']

// ======================= PTX helpers =========================================
__device__ __forceinline__ uint32_t smem_u32(const void* p) {
    uint32_t a;
    asm("{ .reg .u64 t; cvta.to.shared.u64 t, %1; cvt.u32.u64 %0, t; }" : "=r"(a) : "l"(p));
    return a;
}
__device__ __forceinline__ void cp16(uint32_t smem, const void* g) {
    asm volatile("cp.async.cg.shared.global [%0], [%1], 16;" :: "r"(smem), "l"(g));
}
#define CP_COMMIT() asm volatile("cp.async.commit_group;" ::: "memory")
#define CP_WAIT0()  asm volatile("cp.async.wait_group 0;" ::: "memory")
#define CP_WAIT1()  asm volatile("cp.async.wait_group 1;" ::: "memory")

__device__ __forceinline__ void ldm_x4(uint32_t* r, uint32_t addr) {
    asm volatile("ldmatrix.sync.aligned.m8n8.x4.shared.b16 {%0,%1,%2,%3}, [%4];"
                 : "=r"(r[0]), "=r"(r[1]), "=r"(r[2]), "=r"(r[3]) : "r"(addr));
}
__device__ __forceinline__ void mma16816(float* d, const uint32_t* a, const uint32_t* b) {
    asm volatile(
        "mma.sync.aligned.m16n8k16.row.col.f32.f16.f16.f32 "
        "{%0,%1,%2,%3}, {%4,%5,%6,%7}, {%8,%9}, {%0,%1,%2,%3};"
        : "+f"(d[0]), "+f"(d[1]), "+f"(d[2]), "+f"(d[3])
        : "r"(a[0]), "r"(a[1]), "r"(a[2]), "r"(a[3]), "r"(b[0]), "r"(b[1]));
}

// ======================= mma.sync fp16 GEMM + fused col stats ================
// Template: CYCLE_A -> A index masked by (Ka-1) (A K-cycled single plane);
//           SCALE_OUT -> epilogue multiplies acc by 2^-12 (exact).
// CTA tile 128x128, K-stage 64 (128B XOR-swizzled rows), 8 warps (2x4, 64x32),
// 3-stage cp.async pipeline.  (Round-10 proven configuration.)
#define STAGE_BYTES 16384   // 128 rows * 128B
#define NSTAGE 3
#define GEMM_SMEM   (2 * NSTAGE * STAGE_BYTES)   // 98304

template<bool CYCLE_A, bool SCALE_OUT>
__global__ __launch_bounds__(256)
void k_mma_gemm(const __half* __restrict__ A,
                const __half* __restrict__ Bw,
                const float* __restrict__ bias,
                float* __restrict__ C,
                float* __restrict__ part,
                int N, int Ka, int Keff,
                size_t strideB, size_t strideC, size_t strideP)
{
    extern __shared__ __align__(128) char smem[];
    const uint32_t sA = smem_u32(smem);
    const uint32_t sB = sA + NSTAGE * STAGE_BYTES;
    const int tid  = threadIdx.x;
    const int wid  = tid >> 5, lane = tid & 31;
    const int wm   = wid >> 2, wn = wid & 3;

    Bw   += (size_t)blockIdx.z * strideB;
    C    += (size_t)blockIdx.z * strideC;
    part += (size_t)blockIdx.z * strideP;

    const int KaRow = CYCLE_A ? Ka : Keff;     // A row pitch
    const __half* Ab = A  + (size_t)blockIdx.y * 128 * (size_t)KaRow;
    const __half* Bb = Bw + (size_t)blockIdx.x * 128 * (size_t)Keff;
    const int S = Keff >> 6;

    float acc[4][4][4];
#pragma unroll
    for (int mi = 0; mi < 4; mi++)
#pragma unroll
        for (int ni = 0; ni < 4; ni++)
#pragma unroll
            for (int j = 0; j < 4; j++) acc[mi][ni][j] = 0.f;

    auto load_stage = [&](int s, int buf) {
        int kb  = s << 6;
        int kba = CYCLE_A ? (kb & (Ka - 1)) : kb;
        const __half* Ag = Ab + kba;
        const __half* Bg = Bb + kb;
#pragma unroll
        for (int i = 0; i < 4; i++) {
            int q = tid + (i << 8);            // 0..1023 chunk id
            int r = q >> 3, c = q & 7;
            uint32_t off = (uint32_t)r * 128 + (uint32_t)((c ^ (r & 7)) << 4);
            cp16(sA + buf * STAGE_BYTES + off, Ag + (size_t)r * KaRow + (c << 3));
            cp16(sB + buf * STAGE_BYTES + off, Bg + (size_t)r * Keff + (c << 3));
        }
    };

    load_stage(0, 0);
    CP_COMMIT();
    if (S > 1) { load_stage(1, 1); CP_COMMIT(); }

    for (int s = 0; s < S; s++) {
        int buf = s % NSTAGE;
        if (s + 1 < S) CP_WAIT1(); else CP_WAIT0();
        __syncthreads();
        if (s + 2 < S) { load_stage(s + 2, (s + 2) % NSTAGE); CP_COMMIT(); }

        uint32_t bA = sA + buf * STAGE_BYTES;
        uint32_t bB = sB + buf * STAGE_BYTES;
#pragma unroll
        for (int kk = 0; kk < 4; kk++) {
            uint32_t afr[4][4];
#pragma unroll
            for (int mi = 0; mi < 4; mi++) {
                int row = wm * 64 + mi * 16 + (lane & 15);
                int c   = (kk << 1) + (lane >> 4);
                ldm_x4(afr[mi], bA + (uint32_t)row * 128 + (uint32_t)((c ^ (row & 7)) << 4));
            }
            uint32_t bfr[4][2];
#pragma unroll
            for (int np = 0; np < 2; np++) {
                int g  = lane >> 3;                       // 0..3
                int nr = wn * 32 + np * 16 + (g >> 1) * 8 + (lane & 7);
                int c  = (kk << 1) + (g & 1);
                uint32_t tmp[4];
                ldm_x4(tmp, bB + (uint32_t)nr * 128 + (uint32_t)((c ^ (nr & 7)) << 4));
                bfr[np * 2 + 0][0] = tmp[0]; bfr[np * 2 + 0][1] = tmp[1];
                bfr[np * 2 + 1][0] = tmp[2]; bfr[np * 2 + 1][1] = tmp[3];
            }
#pragma unroll
            for (int mi = 0; mi < 4; mi++)
#pragma unroll
                for (int ni = 0; ni < 4; ni++)
                    mma16816(acc[mi][ni], afr[mi], bfr[ni]);
        }
        // no bottom sync: buffer reuse distance is 3 stages; top barrier orders.
    }

    // ---------------- epilogue: (unscale,) bias, store C, fused col stats ---
    if (SCALE_OUT) {
#pragma unroll
        for (int mi = 0; mi < 4; mi++)
#pragma unroll
            for (int ni = 0; ni < 4; ni++)
#pragma unroll
                for (int j = 0; j < 4; j++) acc[mi][ni][j] *= SCALE_DN;  // exact
    }
    int grow = lane >> 2;
    int gcol = (lane & 3) * 2;
    if (bias) {
#pragma unroll
        for (int ni = 0; ni < 4; ni++) {
            int cc = blockIdx.x * 128 + wn * 32 + ni * 8 + gcol;
            float b0 = bias[cc], b1 = bias[cc + 1];
#pragma unroll
            for (int mi = 0; mi < 4; mi++) {
                acc[mi][ni][0] += b0; acc[mi][ni][1] += b1;
                acc[mi][ni][2] += b0; acc[mi][ni][3] += b1;
            }
        }
    }
#pragma unroll
    for (int mi = 0; mi < 4; mi++) {
        int r0 = blockIdx.y * 128 + wm * 64 + mi * 16 + grow;
#pragma unroll
        for (int ni = 0; ni < 4; ni++) {
            int cc = blockIdx.x * 128 + wn * 32 + ni * 8 + gcol;
            *reinterpret_cast<float2*>(C + (size_t)r0 * N + cc) =
                make_float2(acc[mi][ni][0], acc[mi][ni][1]);
            *reinterpret_cast<float2*>(C + (size_t)(r0 + 8) * N + cc) =
                make_float2(acc[mi][ni][2], acc[mi][ni][3]);
        }
    }
    int rowgrp = blockIdx.y * 2 + wm;
#pragma unroll
    for (int ni = 0; ni < 4; ni++) {
#pragma unroll
        for (int jj = 0; jj < 2; jj++) {
            float s = 0.f, q = 0.f;
#pragma unroll
            for (int mi = 0; mi < 4; mi++) {
                float v0 = acc[mi][ni][jj], v1 = acc[mi][ni][jj + 2];
                s += v0 + v1;
                q += v0 * v0 + v1 * v1;
            }
#pragma unroll
            for (int o = 4; o < 32; o <<= 1) {
                s += __shfl_xor_sync(0xffffffffu, s, o);
                q += __shfl_xor_sync(0xffffffffu, q, o);
            }
            if (grow == 0) {
                int cc = blockIdx.x * 128 + wn * 32 + ni * 8 + gcol + jj;
                size_t idx = ((size_t)rowgrp * N + cc) * 2;
                part[idx]     = s;
                part[idx + 1] = q;
            }
        }
    }
}

// ======================= stats finalize (merged over branches via y) =========
__global__ void k_colstats_fin(const float* __restrict__ part,
                               float* __restrict__ mu, float* __restrict__ rstd,
                               int cols, size_t pstride) {
    part += (size_t)blockIdx.y * pstride;
    mu   += (size_t)blockIdx.y * cols;
    rstd += (size_t)blockIdx.y * cols;
    int c = blockIdx.x * 256 + threadIdx.x;
    if (c >= cols) return;
    float s = 0.f, cs = 0.f, q = 0.f, cq = 0.f;
    for (int rg = 0; rg < 128; rg++) {
        float vs = part[((size_t)rg * cols + c) * 2 + 0];
        float vq = part[((size_t)rg * cols + c) * 2 + 1];
        float y1 = vs - cs; float t1 = s + y1; cs = (t1 - s) - y1; s = t1;
        float y2 = vq - cq; float t2 = q + y2; cq = (t2 - q) - y2; q = t2;
    }
    const float invn = 1.0f / 8192.0f;
    float m = s * invn;
    float var = q * invn - m * m;
    mu[c] = m;
    rstd[c] = 1.0f / sqrtf(var + 1e-5f);
}

// ======================= merged weight splits (4 weights, one launch) ========
// y = 0..2: branch [hi | mid*2^12] (K=512); y = 3: proj folded [hi*2^12 | mid'] (K=4096)
__global__ void k_splits(const float* __restrict__ w0, const float* __restrict__ w1,
                         const float* __restrict__ w2, const float* __restrict__ w3,
                         __half* __restrict__ dwc, __half* __restrict__ dwp,
                         int NK) {
    int i4 = (blockIdx.x * 256 + threadIdx.x) * 4;
    if (i4 >= NK) return;
    int y = blockIdx.y;
    const float* w = (y == 0) ? w0 : (y == 1) ? w1 : (y == 2) ? w2 : w3;
    float4 v = *reinterpret_cast<const float4*>(w + i4);
    float vv[4] = { v.x, v.y, v.z, v.w };
    __half p0[4], p1[4];
    if (y < 3) {
#pragma unroll
        for (int j = 0; j < 4; j++) {
            p0[j] = __float2half_rn(vv[j]);                          // hi
            float r1 = vv[j] - __half2float(p0[j]);
            p1[j] = __float2half_rn(r1 * SCALE_UP);                  // mid*2^12
        }
        int K = 512;
        int n = i4 >> 9, kk = i4 & 511;
        __half* d = dwc + (size_t)y * DH_ * 1024;
        size_t base = (size_t)n * 2 * K + kk;
        *reinterpret_cast<uint2*>(d + base)     = *reinterpret_cast<uint2*>(p0);
        *reinterpret_cast<uint2*>(d + base + K) = *reinterpret_cast<uint2*>(p1);
    } else {
#pragma unroll
        for (int j = 0; j < 4; j++) {
            __half h = __float2half_rn(vv[j]);
            float hf = __half2float(h);
            p0[j] = __float2half_rn(hf * SCALE_UP);                  // hi*2^12 (exact)
            p1[j] = __float2half_rn((vv[j] - hf) * SCALE_UP);        // mid'
        }
        int K = 4096;
        int n = i4 >> 12, kk = i4 & 4095;
        size_t base = (size_t)n * 2 * K + kk;
        *reinterpret_cast<uint2*>(dwp + base)     = *reinterpret_cast<uint2*>(p0);
        *reinterpret_cast<uint2*>(dwp + base + K) = *reinterpret_cast<uint2*>(p1);
    }
}

// ======================= elementwise stages ==================================
// shortcut LIF -> dual-half spikes [s | s*2^-12], vec x4 (round-10)
__global__ void k_lif_in(const float* __restrict__ x) {
    int i4 = (blockIdx.x * 256 + threadIdx.x) * 4;
    if (i4 >= BD_) return;
    int b = i4 >> 9, d2 = i4 & 511;
    float v[4] = { 0.f, 0.f, 0.f, 0.f };
#pragma unroll
    for (int t = 0; t < T_; t++) {
        float4 xt = *reinterpret_cast<const float4*>(x + t * BD_ + i4);
        float xv[4] = { xt.x, xt.y, xt.z, xt.w };
        __half s[4], sd[4];
#pragma unroll
        for (int j = 0; j < 4; j++) {
            float dta = xv[j] - v[j];
            v[j] = v[j] + dta * 0.5f;
            float sp = (v[j] - 1.0f) >= 0.0f ? 1.0f : 0.0f;
            s[j]  = __float2half(sp);
            sd[j] = __float2half(sp * SCALE_DN);
            v[j] = v[j] * (1.0f - sp);
        }
        size_t base = ((size_t)(t * B_ + b)) * 1024 + d2;
        *reinterpret_cast<uint2*>(g_xs + base)       = *reinterpret_cast<uint2*>(s);
        *reinterpret_cast<uint2*>(g_xs + base + 512) = *reinterpret_cast<uint2*>(sd);
    }
}

// mega-fused BN+LIF, phase-per-branch with spike bitmasks (bit-identical):
// per (b,dd) thread: q-phase, k-phase, v-phase (each over t,h with exact
// same per-element FP ops as before), spikes packed into uint32 (bit t*8+h);
// kv = popc(k&v per t) == exact float sum of 0/1 products; kv-LIF; P writes.
__global__ __launch_bounds__(128)
void k_bnlif_kv(const float* __restrict__ Y,
                const float* __restrict__ mu, const float* __restrict__ rstd,
                const float* __restrict__ gq, const float* __restrict__ bq,
                const float* __restrict__ gk, const float* __restrict__ bk,
                const float* __restrict__ gv, const float* __restrict__ bv,
                float* __restrict__ vout, __half* __restrict__ P)
{
    int i = blockIdx.x * 128 + threadIdx.x;
    if (i >= BD_) return;
    int b = i >> 9, dd = i & 511;
    int c0 = dd << 3;

    uint32_t qbits = 0, kbits = 0, vbits = 0;

#pragma unroll
    for (int br = 0; br < 3; br++) {
        const float* Yb = Y + (size_t)br * TBDH_;
        const float* gg = (br == 0) ? gq : (br == 1) ? gk : gv;
        const float* bb = (br == 0) ? bq : (br == 1) ? bk : bv;
        float m[8], rs[8], ga[8], ba[8];
#pragma unroll
        for (int h = 0; h < 8; h++) {
            m[h]  = mu[br * DH_ + c0 + h];
            rs[h] = rstd[br * DH_ + c0 + h];
            ga[h] = gg[c0 + h];
            ba[h] = bb[c0 + h];
        }
        float u[8];
#pragma unroll
        for (int h = 0; h < 8; h++) u[h] = 0.f;
        uint32_t bits = 0;
#pragma unroll
        for (int t = 0; t < T_; t++) {
            int row = t * B_ + b;
            size_t rb = (size_t)row * DH_ + c0;
            float xv[8];
            *reinterpret_cast<float4*>(&xv[0]) = *reinterpret_cast<const float4*>(Yb + rb);
            *reinterpret_cast<float4*>(&xv[4]) = *reinterpret_cast<const float4*>(Yb + rb + 4);
#pragma unroll
            for (int h = 0; h < 8; h++) {
                float y = ga[h] * (xv[h] - m[h]); y *= rs[h]; y += ba[h];
                float d = y - u[h]; u[h] = u[h] + d * 0.5f;
                bool sp = (u[h] - 1.0f) >= 0.f;
                float s = sp ? 1.f : 0.f;
                bits |= (uint32_t)sp << (t * 8 + h);
                u[h] *= (1.f - s);
                if (br == 2)
                    vout[(size_t)row * DH_ + dd + (h << 9)] = s;
            }
        }
        if (br == 0) qbits = bits; else if (br == 1) kbits = bits; else vbits = bits;
    }

    float ukv = 0.f;
    const __half h1 = __float2half(1.0f);
    const __half h0 = __float2half(0.0f);
#pragma unroll
    for (int t = 0; t < T_; t++) {
        uint32_t mask = (kbits >> (t * 8)) & (vbits >> (t * 8)) & 0xFFu;
        float kv = (float)__popc(mask);        // exact small integer
        float d2 = kv - ukv; ukv = ukv + d2 * 0.5f;
        bool skvp = (ukv - 0.5f) >= 0.f;
        float skv = skvp ? 1.f : 0.f; ukv *= (1.f - skv);
        int row = t * B_ + b;
        size_t pb = (size_t)row * 4096 + dd;
        uint32_t sqt = skvp ? ((qbits >> (t * 8)) & 0xFFu) : 0u;
#pragma unroll
        for (int h = 0; h < 8; h++)
            P[pb + (h << 9)] = ((sqt >> h) & 1u) ? h1 : h0;
    }
}

// final BN + residual, 4 elements/thread
__global__ void k_bn_add(const float* __restrict__ x, const float* __restrict__ gp,
                         const float* __restrict__ bp, float* __restrict__ out) {
    int i4 = (blockIdx.x * 256 + threadIdx.x) * 4;
    if (i4 >= TBD_) return;
    int c = i4 & 511;
    float4 v  = *reinterpret_cast<const float4*>(g_opre + i4);
    float4 xr = *reinterpret_cast<const float4*>(x + i4);
    float4 mg = *reinterpret_cast<const float4*>(g_omu + c);
    float4 rg = *reinterpret_cast<const float4*>(g_orstd + c);
    float4 gg = *reinterpret_cast<const float4*>(gp + c);
    float4 bb = *reinterpret_cast<const float4*>(bp + c);
    float vv[4] = { v.x, v.y, v.z, v.w };
    float xx[4] = { xr.x, xr.y, xr.z, xr.w };
    float mm[4] = { mg.x, mg.y, mg.z, mg.w };
    float rr[4] = { rg.x, rg.y, rg.z, rg.w };
    float ga[4] = { gg.x, gg.y, gg.z, gg.w };
    float ba[4] = { bb.x, bb.y, bb.z, bb.w };
    float o[4];
#pragma unroll
    for (int j = 0; j < 4; j++) {
        float y = ga[j] * (vv[j] - mm[j]);
        y = y * rr[j];
        y = y + ba[j];
        o[j] = y + xx[j];
    }
    *reinterpret_cast<float4*>(out + i4) =
        make_float4(o[0], o[1], o[2], o[3]);
}

// ======================= launch ==============================================
extern "C" void kernel_launch(void* const* d_in, const int* in_sizes, int n_in,
                              void* d_out, int out_size) {
    const float* x     = (const float*)d_in[0];
    const float* wq    = (const float*)d_in[1];
    const float* gq    = (const float*)d_in[2];
    const float* bq    = (const float*)d_in[3];
    const float* wk    = (const float*)d_in[4];
    const float* gk    = (const float*)d_in[5];
    const float* bk    = (const float*)d_in[6];
    const float* wv    = (const float*)d_in[7];
    const float* gv    = (const float*)d_in[8];
    const float* bv    = (const float*)d_in[9];
    const float* wproj = (const float*)d_in[10];
    const float* bproj = (const float*)d_in[11];
    const float* gp    = (const float*)d_in[12];
    const float* bp    = (const float*)d_in[13];

    float* out  = (float*)d_out;
    float* vout = out + TBD_;

    __half *p_xs, *p_p, *p_wc, *p_wp;
    float *p_ypre, *p_opre;
    float *p_mu, *p_rstd, *p_omu, *p_orstd, *p_part, *p_opart;
    cudaGetSymbolAddress((void**)&p_xs,    g_xs);
    cudaGetSymbolAddress((void**)&p_ypre,  g_ypre);
    cudaGetSymbolAddress((void**)&p_p,     g_p);
    cudaGetSymbolAddress((void**)&p_opre,  g_opre);
    cudaGetSymbolAddress((void**)&p_mu,    g_mu);
    cudaGetSymbolAddress((void**)&p_rstd,  g_rstd);
    cudaGetSymbolAddress((void**)&p_omu,   g_omu);
    cudaGetSymbolAddress((void**)&p_orstd, g_orstd);
    cudaGetSymbolAddress((void**)&p_part,  g_part);
    cudaGetSymbolAddress((void**)&p_opart, g_opart);
    cudaGetSymbolAddress((void**)&p_wc,    g_wc);
    cudaGetSymbolAddress((void**)&p_wp,    g_wp);

    cudaFuncSetAttribute(k_mma_gemm<false, false>,
                         cudaFuncAttributeMaxDynamicSharedMemorySize, GEMM_SMEM);
    cudaFuncSetAttribute(k_mma_gemm<true, true>,
                         cudaFuncAttributeMaxDynamicSharedMemorySize, GEMM_SMEM);

    // 0) all 4 weight splits in one launch (y = 0..3)
    const int nkb = DH_ * D_;
    k_splits<<<dim3((nkb / 4 + 255) / 256, 4), 256>>>(wq, wk, wv, wproj,
                                                      p_wc, p_wp, nkb);

    // 1) shortcut LIF -> dual-half spikes, vec x4
    k_lif_in<<<BD_ / 1024, 256>>>(x);

    // 2) three branch GEMMs in one launch (z = branch), Keff = 1024 contiguous
    const size_t PSTRIDE = 128ULL * DH_ * 2;
    k_mma_gemm<false, false><<<dim3(DH_ / 128, TB_ / 128, 3), 256, GEMM_SMEM>>>(
        p_xs, p_wc, nullptr, p_ypre, p_part,
        DH_, 1024, 1024, (size_t)DH_ * 1024, TBDH_, PSTRIDE);

    // 3) finalize BN stats for all 3 branches in one launch
    k_colstats_fin<<<dim3(DH_ / 256, 3), 256>>>(p_part, p_mu, p_rstd, DH_, PSTRIDE);

    // 4) mega-fused BN+LIF(q,k,v) + kv + LIF(0.5) + p (bitmask phases, 128 thr)
    k_bnlif_kv<<<BD_ / 128, 128>>>(p_ypre, p_mu, p_rstd, gq, bq, gk, bk, gv, bv,
                                   vout, p_p);

    // 5) proj GEMM: single-plane A K-cycled 4096->8192 (+bias), epilogue 2^-12
    k_mma_gemm<true, true><<<dim3(D_ / 128, TB_ / 128, 1), 256, GEMM_SMEM>>>(
        p_p, p_wp, bproj, p_opre, p_opart,
        D_, 4096, 8192, 0, 0, 0);

    // 6) finalize proj stats
    k_colstats_fin<<<dim3(D_ / 256, 1), 256>>>(p_opart, p_omu, p_orstd, D_, 0);

    // 7) final BN + residual, vec x4
    k_bn_add<<<TBD_ / 1024, 256>>>(x, gp, bp, out);
}